// round 14
// baseline (speedup 1.0000x reference)
#include <cuda_runtime.h>
#include <math.h>
#include <stdint.h>

// ---------------------------------------------------------------------------
// Problem constants
// ---------------------------------------------------------------------------
#define BATCH  4
#define NTOK   1024
#define DMODEL 1024
#define HEADS  16
#define HDIM   64
#define ROWS   (BATCH * NTOK)     // 4096
#define MLPD   4096
#define SIXD   (6 * DMODEL)       // 6144
#define EPS    1e-6f

// ---------------------------------------------------------------------------
// Scratch (device globals: no allocations allowed)
// ---------------------------------------------------------------------------
__device__ float g_mod[BATCH * SIXD];
__device__ float g_h  [ROWS * DMODEL];      // K-permuted (GEMM A operand)
__device__ float g_q  [ROWS * DMODEL];      // natural (attention input)
__device__ float g_kv [ROWS * 2 * DMODEL];  // natural (attention input)
__device__ float g_att[ROWS * DMODEL];      // K-permuted (Wo A operand)
__device__ float g_m1 [ROWS * MLPD];        // K-permuted (W2 A operand)
// tf32-rounded, row-permuted weights; Wq|Wkv fused into [1024][3072]
__device__ float g_wqkv[DMODEL * 3 * DMODEL];
__device__ float g_wo  [DMODEL * DMODEL];
__device__ float g_w1  [DMODEL * MLPD];
__device__ float g_w2  [MLPD * DMODEL];

// ---------------------------------------------------------------------------
// Helpers
// ---------------------------------------------------------------------------
// K-dim permutation within each group of 8: j -> 2j (j<4), 2j-7 (j>=4).
__device__ __forceinline__ int kperm(int k) {
    return (k & ~7) | (((k & 3) << 1) | ((k >> 2) & 1));
}

__device__ __forceinline__ float gelu_tanh(float y) {
    float y3 = y * y * y;
    return 0.5f * y * (1.0f + tanhf(0.7978845608028654f * (y + 0.044715f * y3)));
}

__device__ __forceinline__ float to_tf32(float x) {
    uint32_t y;
    asm("cvt.rna.tf32.f32 %0, %1;" : "=r"(y) : "f"(x));
    return __uint_as_float(y);
}

__device__ __forceinline__ void cp_async16(void* smem_dst, const void* gmem_src) {
    uint32_t s = (uint32_t)__cvta_generic_to_shared(smem_dst);
    asm volatile("cp.async.cg.shared.global [%0], [%1], 16;\n"
                 :: "r"(s), "l"(gmem_src));
}
__device__ __forceinline__ void cp_commit() {
    asm volatile("cp.async.commit_group;\n");
}
template <int N>
__device__ __forceinline__ void cp_wait() {
    asm volatile("cp.async.wait_group %0;\n" :: "n"(N));
}

__device__ __forceinline__ void mma_tf32(
    float& d0, float& d1, float& d2, float& d3,
    uint32_t a0, uint32_t a1, uint32_t a2, uint32_t a3,
    uint32_t b0, uint32_t b1)
{
    asm volatile(
        "mma.sync.aligned.m16n8k8.row.col.f32.tf32.tf32.f32 "
        "{%0,%1,%2,%3}, {%4,%5,%6,%7}, {%8,%9}, {%0,%1,%2,%3};"
        : "+f"(d0), "+f"(d1), "+f"(d2), "+f"(d3)
        : "r"(a0), "r"(a1), "r"(a2), "r"(a3), "r"(b0), "r"(b1));
}

// ---------------------------------------------------------------------------
// Kernel 0: round ALL weights to tf32 + permute K-dim rows, one launch.
// ---------------------------------------------------------------------------
__global__ void __launch_bounds__(256) round_weights_kernel(
    const float4* __restrict__ Wq, const float4* __restrict__ Wkv,
    const float4* __restrict__ Wo, const float4* __restrict__ W1,
    const float4* __restrict__ W2,
    float4* __restrict__ wqkv, float4* __restrict__ wo,
    float4* __restrict__ w1, float4* __restrict__ w2)
{
    const int t = blockIdx.y;
    const int i = blockIdx.x * 256 + threadIdx.x;
    const float4* src = nullptr;
    float4* dst = nullptr;
    int n4 = 0, di = 0;
    switch (t) {
        case 0: n4 = DMODEL * DMODEL / 4;     src = Wq;  dst = wqkv;
                di = kperm(i >> 8) * 768 + (i & 255); break;
        case 1: n4 = DMODEL * 2 * DMODEL / 4; src = Wkv; dst = wqkv;
                di = kperm(i >> 9) * 768 + 256 + (i & 511); break;
        case 2: n4 = DMODEL * DMODEL / 4;     src = Wo;  dst = wo;
                di = kperm(i >> 8) * 256 + (i & 255); break;
        case 3: n4 = DMODEL * MLPD / 4;       src = W1;  dst = w1;
                di = kperm(i >> 10) * 1024 + (i & 1023); break;
        case 4: n4 = MLPD * DMODEL / 4;       src = W2;  dst = w2;
                di = kperm(i >> 8) * 256 + (i & 255); break;
    }
    if (i < n4) {
        float4 v = src[i];
        v.x = to_tf32(v.x); v.y = to_tf32(v.y);
        v.z = to_tf32(v.z); v.w = to_tf32(v.w);
        dst[di] = v;
    }
}

// ---------------------------------------------------------------------------
// Kernel 1: mod = silu(c) @ Wada + bada        [4, 6144]
// ---------------------------------------------------------------------------
__global__ void __launch_bounds__(256) ada_mod_kernel(
    const float* __restrict__ c, const float* __restrict__ Wada,
    const float* __restrict__ bada, float* __restrict__ mod)
{
    __shared__ float sc[DMODEL];
    int b = blockIdx.y;
    int n = blockIdx.x * 256 + threadIdx.x;
    for (int i = threadIdx.x; i < DMODEL; i += 256) {
        float v = c[b * DMODEL + i];
        sc[i] = v / (1.0f + __expf(-v));
    }
    __syncthreads();
    float acc = 0.0f;
    const float* wp = Wada + n;
    for (int k = 0; k < DMODEL; k++)
        acc = fmaf(sc[k], wp[(size_t)k * SIXD], acc);
    mod[b * SIXD + n] = acc + bada[n];
}

// ---------------------------------------------------------------------------
// Kernel 2: out = tf32(LN(x) * (1 + scale) + shift), K-permuted store
// ---------------------------------------------------------------------------
__global__ void __launch_bounds__(256) ln_mod_kernel(
    const float* __restrict__ x, const float* __restrict__ mod,
    int shiftOff, int scaleOff, float* __restrict__ out)
{
    __shared__ float red[8];
    int row = blockIdx.x;
    int b = row >> 10;
    const float4* xr = (const float4*)(x + (size_t)row * DMODEL);
    float4 v = xr[threadIdx.x];

    float s = v.x + v.y + v.z + v.w;
    #pragma unroll
    for (int o = 16; o; o >>= 1) s += __shfl_xor_sync(0xffffffffu, s, o);
    if ((threadIdx.x & 31) == 0) red[threadIdx.x >> 5] = s;
    __syncthreads();
    float tot = 0.f;
    #pragma unroll
    for (int w = 0; w < 8; w++) tot += red[w];
    float mean = tot * (1.0f / DMODEL);
    __syncthreads();

    float dx = v.x - mean, dy = v.y - mean, dz = v.z - mean, dw = v.w - mean;
    float q = dx * dx + dy * dy + dz * dz + dw * dw;
    #pragma unroll
    for (int o = 16; o; o >>= 1) q += __shfl_xor_sync(0xffffffffu, q, o);
    if ((threadIdx.x & 31) == 0) red[threadIdx.x >> 5] = q;
    __syncthreads();
    float vtot = 0.f;
    #pragma unroll
    for (int w = 0; w < 8; w++) vtot += red[w];
    float rstd = rsqrtf(vtot * (1.0f / DMODEL) + EPS);

    int c0 = threadIdx.x * 4;
    const float* base = mod + (size_t)b * SIXD;
    float4 shv = *(const float4*)(base + shiftOff + c0);
    float4 scv = *(const float4*)(base + scaleOff + c0);
    float* orow = out + (size_t)row * DMODEL;
    orow[kperm(c0 + 0)] = to_tf32(dx * rstd * (1.0f + scv.x) + shv.x);
    orow[kperm(c0 + 1)] = to_tf32(dy * rstd * (1.0f + scv.y) + shv.y);
    orow[kperm(c0 + 2)] = to_tf32(dz * rstd * (1.0f + scv.z) + shv.z);
    orow[kperm(c0 + 3)] = to_tf32(dw * rstd * (1.0f + scv.w) + shv.w);
}

// ---------------------------------------------------------------------------
// Kernel 3: TF32 mma.sync GEMM, cp.async 3-stage pipeline, ONE sync/tile.
// 8 warps (256 threads), warp tile 64 x (BN/4). BN=128 (big-N GEMMs) or
// BN=64 (N=1024 GEMMs: 512 blocks instead of 256 -> better wave balance).
// A and B K-permuted within groups of 8 (A fragments load as LDS.64).
//   EPI 1: C = tf32(gelu(acc + bias[n])), K-permuted store (feeds W2)
//   EPI 2: C = res + gate * (acc + bias[n])   (natural; exact fp32 residual)
//   EPI 3: qkv split (natural): cols<1024 -> C (+bias), else -> C2 (+bias2)
// ---------------------------------------------------------------------------
#define GSTAGES 3
#define APAD 40
#define GEMM_SMEM(BN) (GSTAGES * (128 * APAD + 32 * (BN + 4)) * (int)sizeof(float))

template <int EPI, int BN>
__global__ void __launch_bounds__(256, 2) mma_gemm_kernel(
    const float* __restrict__ A, const float* __restrict__ B,
    const float* __restrict__ bias, const float* __restrict__ bias2,
    const float* __restrict__ res, const float* __restrict__ gate,
    float* __restrict__ C, float* __restrict__ C2,
    int M, int N, int K)
{
    constexpr int BPADX = BN + 4;
    constexpr int NF    = BN / 32;          // n-frags per warp (4 or 2)
    constexpr int BSLOT = BN / 4;           // float4 slots per B row
    constexpr int BROWS = 256 / BSLOT;      // k-rows covered per loader iter

    extern __shared__ char smemRaw[];
    float (*As)[128][APAD]  = reinterpret_cast<float(*)[128][APAD]>(smemRaw);
    float (*Bs)[32][BPADX]  = reinterpret_cast<float(*)[32][BPADX]>(
        smemRaw + GSTAGES * 128 * APAD * sizeof(float));

    const int tid  = threadIdx.x;
    const int lane = tid & 31;
    const int warp = tid >> 5;
    const int wm   = warp & 1;              // 2 m-bands of 64
    const int wn   = warp >> 1;             // 4 n-bands of BN/4
    const int bm   = blockIdx.y * 128;
    const int bn   = blockIdx.x * BN;

    const int g  = lane >> 2;
    const int tg = lane & 3;

    const int aRow0 = tid >> 3;             // 0..31
    const int aK4   = (tid & 7) * 4;
    const int bK0   = tid / BSLOT;          // 0..BROWS-1
    const int bN4   = (tid % BSLOT) * 4;

    float acc[4][NF][4];
    #pragma unroll
    for (int i = 0; i < 4; i++)
        #pragma unroll
        for (int j = 0; j < NF; j++)
            #pragma unroll
            for (int r = 0; r < 4; r++) acc[i][j][r] = 0.f;

    const int kTiles = K >> 5;

    auto load_tile = [&](int st, int k0) {
        #pragma unroll
        for (int i = 0; i < 4; i++) {
            int r = i * 32 + aRow0;
            cp_async16(&As[st][r][aK4], A + (size_t)(bm + r) * K + k0 + aK4);
        }
        #pragma unroll
        for (int i = 0; i < 32 / BROWS; i++) {
            int kk = i * BROWS + bK0;
            cp_async16(&Bs[st][kk][bN4], B + (size_t)(k0 + kk) * N + bn + bN4);
        }
    };

    #pragma unroll
    for (int s = 0; s < GSTAGES - 1; s++) {
        load_tile(s, s * 32);
        cp_commit();
    }

    for (int it = 0; it < kTiles; it++) {
        cp_wait<GSTAGES - 2>();
        __syncthreads();

        int nxt = it + GSTAGES - 1;
        if (nxt < kTiles)
            load_tile(nxt % GSTAGES, nxt * 32);
        cp_commit();                        // empty commits keep group count uniform

        const int st = it % GSTAGES;
        #pragma unroll
        for (int ks = 0; ks < 4; ks++) {
            const int kb = ks * 8;
            uint32_t a[4][4], b[NF][2];
            #pragma unroll
            for (int mf = 0; mf < 4; mf++) {
                int r = wm * 64 + mf * 16 + g;
                float2 av0 = *(const float2*)&As[st][r    ][kb + 2 * tg];
                float2 av1 = *(const float2*)&As[st][r + 8][kb + 2 * tg];
                a[mf][0] = __float_as_uint(av0.x);
                a[mf][1] = __float_as_uint(av1.x);
                a[mf][2] = __float_as_uint(av0.y);
                a[mf][3] = __float_as_uint(av1.y);
            }
            #pragma unroll
            for (int nf = 0; nf < NF; nf++) {
                int n = wn * (BN / 4) + nf * 8 + g;
                b[nf][0] = __float_as_uint(Bs[st][kb + 2 * tg    ][n]);
                b[nf][1] = __float_as_uint(Bs[st][kb + 2 * tg + 1][n]);
            }
            #pragma unroll
            for (int mf = 0; mf < 4; mf++)
                #pragma unroll
                for (int nf = 0; nf < NF; nf++)
                    mma_tf32(acc[mf][nf][0], acc[mf][nf][1],
                             acc[mf][nf][2], acc[mf][nf][3],
                             a[mf][0], a[mf][1], a[mf][2], a[mf][3],
                             b[nf][0], b[nf][1]);
        }
    }

    #pragma unroll
    for (int mf = 0; mf < 4; mf++) {
        #pragma unroll
        for (int half = 0; half < 2; half++) {
            int row = bm + wm * 64 + mf * 16 + g + half * 8;
            size_t gbase = (size_t)(row >> 10) * SIXD;
            #pragma unroll
            for (int nf = 0; nf < NF; nf++) {
                int col = bn + wn * (BN / 4) + nf * 8 + 2 * tg;
                float y0 = acc[mf][nf][half * 2 + 0];
                float y1 = acc[mf][nf][half * 2 + 1];
                if (EPI == 3) {
                    if (col < DMODEL) {
                        size_t rb = (size_t)row * DMODEL;
                        C[rb + col]     = to_tf32(y0 + bias[col]);
                        C[rb + col + 1] = to_tf32(y1 + bias[col + 1]);
                    } else {
                        int c2 = col - DMODEL;
                        size_t rb = (size_t)row * (2 * DMODEL);
                        C2[rb + c2]     = to_tf32(y0 + bias2[c2]);
                        C2[rb + c2 + 1] = to_tf32(y1 + bias2[c2 + 1]);
                    }
                } else if (EPI == 1) {
                    size_t rbase = (size_t)row * N;
                    C[rbase + kperm(col)]     = to_tf32(gelu_tanh(y0 + bias[col]));
                    C[rbase + kperm(col + 1)] = to_tf32(gelu_tanh(y1 + bias[col + 1]));
                } else {
                    size_t rbase = (size_t)row * N;
                    y0 = res[rbase + col]     + gate[gbase + col]     * (y0 + bias[col]);
                    y1 = res[rbase + col + 1] + gate[gbase + col + 1] * (y1 + bias[col + 1]);
                    C[rbase + col]     = y0;
                    C[rbase + col + 1] = y1;
                }
            }
        }
    }
}

// ---------------------------------------------------------------------------
// Kernel 4: flash attention on tf32 tensor cores
// 8 warps x m16 = 128 q rows per block, Bc=64, d=64.
// K/V tiles fetched via cp.async (no register staging / L1 in the path).
// Output store is K-permuted (att feeds the Wo GEMM as A).
// ---------------------------------------------------------------------------
#define AQ_PAD 68
#define AK_PAD 68
#define AV_PAD 72
#define AP_PAD 68
#define ATTN_SMEM_BYTES ((128 * AQ_PAD + 64 * AK_PAD + 64 * AV_PAD + 128 * AP_PAD) * (int)sizeof(float))

__global__ void __launch_bounds__(256, 2) attn_mma_kernel(
    const float* __restrict__ q, const float* __restrict__ kv,
    float* __restrict__ out)
{
    extern __shared__ float sm[];
    float (*Qs)[AQ_PAD] = reinterpret_cast<float(*)[AQ_PAD]>(sm);
    float (*Ks)[AK_PAD] = reinterpret_cast<float(*)[AK_PAD]>(sm + 128 * AQ_PAD);
    float (*Vs)[AV_PAD] = reinterpret_cast<float(*)[AV_PAD]>(sm + 128 * AQ_PAD + 64 * AK_PAD);
    float (*Ps)[AP_PAD] = reinterpret_cast<float(*)[AP_PAD]>(sm + 128 * AQ_PAD + 64 * AK_PAD + 64 * AV_PAD);

    const int tid  = threadIdx.x;
    const int lane = tid & 31;
    const int warp = tid >> 5;
    const int g    = lane >> 2;
    const int tg   = lane & 3;
    const int b    = blockIdx.y >> 4;
    const int h    = blockIdx.y & 15;
    const int q0   = blockIdx.x * 128;
    const int rg   = warp * 16 + g;

    for (int t = tid; t < 128 * 16; t += 256) {
        int r = t >> 4, d4 = (t & 15) * 4;
        float4 v = *(const float4*)(q +
            ((((size_t)(b * NTOK + q0 + r)) * HEADS + h) << 6) + d4);
        Qs[r][d4 + 0] = v.x * 0.125f; Qs[r][d4 + 1] = v.y * 0.125f;
        Qs[r][d4 + 2] = v.z * 0.125f; Qs[r][d4 + 3] = v.w * 0.125f;
    }

    float o[8][4];
    #pragma unroll
    for (int nf = 0; nf < 8; nf++)
        #pragma unroll
        for (int r = 0; r < 4; r++) o[nf][r] = 0.f;
    float m0 = -INFINITY, m1 = -INFINITY, l0 = 0.f, l1 = 0.f;

    for (int jt = 0; jt < NTOK / 64; jt++) {
        int j0 = jt * 64;
        __syncthreads();   // WAR: previous iter's reads of Ks/Vs complete
        {
            // 4 rows' worth of K + V chunks per thread via cp.async
            #pragma unroll
            for (int i = 0; i < 4; i++) {
                int t = tid + i * 256;
                int r = t >> 4, d4 = (t & 15) * 4;
                size_t base = (size_t)(b * NTOK + j0 + r) * (2 * DMODEL) + h * HDIM + d4;
                cp_async16(&Ks[r][d4], kv + base);
                cp_async16(&Vs[r][d4], kv + base + DMODEL);
            }
            cp_commit();
            cp_wait<0>();
        }
        __syncthreads();

        float s[8][4];
        #pragma unroll
        for (int nf = 0; nf < 8; nf++)
            #pragma unroll
            for (int r = 0; r < 4; r++) s[nf][r] = 0.f;
        #pragma unroll
        for (int kb = 0; kb < 64; kb += 8) {
            uint32_t a0 = __float_as_uint(Qs[rg    ][kb + tg    ]);
            uint32_t a1 = __float_as_uint(Qs[rg + 8][kb + tg    ]);
            uint32_t a2 = __float_as_uint(Qs[rg    ][kb + tg + 4]);
            uint32_t a3 = __float_as_uint(Qs[rg + 8][kb + tg + 4]);
            #pragma unroll
            for (int nf = 0; nf < 8; nf++) {
                uint32_t b0 = __float_as_uint(Ks[nf * 8 + g][kb + tg    ]);
                uint32_t b1 = __float_as_uint(Ks[nf * 8 + g][kb + tg + 4]);
                mma_tf32(s[nf][0], s[nf][1], s[nf][2], s[nf][3],
                         a0, a1, a2, a3, b0, b1);
            }
        }

        float mx0 = -INFINITY, mx1 = -INFINITY;
        #pragma unroll
        for (int nf = 0; nf < 8; nf++) {
            mx0 = fmaxf(mx0, fmaxf(s[nf][0], s[nf][1]));
            mx1 = fmaxf(mx1, fmaxf(s[nf][2], s[nf][3]));
        }
        mx0 = fmaxf(mx0, __shfl_xor_sync(0xffffffffu, mx0, 1));
        mx0 = fmaxf(mx0, __shfl_xor_sync(0xffffffffu, mx0, 2));
        mx1 = fmaxf(mx1, __shfl_xor_sync(0xffffffffu, mx1, 1));
        mx1 = fmaxf(mx1, __shfl_xor_sync(0xffffffffu, mx1, 2));
        float mN0 = fmaxf(m0, mx0), mN1 = fmaxf(m1, mx1);
        float c0 = __expf(m0 - mN0), c1 = __expf(m1 - mN1);
        float sum0 = 0.f, sum1 = 0.f;
        #pragma unroll
        for (int nf = 0; nf < 8; nf++) {
            s[nf][0] = __expf(s[nf][0] - mN0); sum0 += s[nf][0];
            s[nf][1] = __expf(s[nf][1] - mN0); sum0 += s[nf][1];
            s[nf][2] = __expf(s[nf][2] - mN1); sum1 += s[nf][2];
            s[nf][3] = __expf(s[nf][3] - mN1); sum1 += s[nf][3];
        }
        sum0 += __shfl_xor_sync(0xffffffffu, sum0, 1);
        sum0 += __shfl_xor_sync(0xffffffffu, sum0, 2);
        sum1 += __shfl_xor_sync(0xffffffffu, sum1, 1);
        sum1 += __shfl_xor_sync(0xffffffffu, sum1, 2);
        l0 = l0 * c0 + sum0; l1 = l1 * c1 + sum1;
        m0 = mN0; m1 = mN1;
        #pragma unroll
        for (int nf = 0; nf < 8; nf++) {
            o[nf][0] *= c0; o[nf][1] *= c0;
            o[nf][2] *= c1; o[nf][3] *= c1;
        }

        #pragma unroll
        for (int nf = 0; nf < 8; nf++) {
            int col = nf * 8 + 2 * tg;
            Ps[rg    ][col] = to_tf32(s[nf][0]); Ps[rg    ][col + 1] = to_tf32(s[nf][1]);
            Ps[rg + 8][col] = to_tf32(s[nf][2]); Ps[rg + 8][col + 1] = to_tf32(s[nf][3]);
        }
        __syncwarp();

        #pragma unroll
        for (int kb = 0; kb < 64; kb += 8) {
            uint32_t a0 = __float_as_uint(Ps[rg    ][kb + tg    ]);
            uint32_t a1 = __float_as_uint(Ps[rg + 8][kb + tg    ]);
            uint32_t a2 = __float_as_uint(Ps[rg    ][kb + tg + 4]);
            uint32_t a3 = __float_as_uint(Ps[rg + 8][kb + tg + 4]);
            #pragma unroll
            for (int nf = 0; nf < 8; nf++) {
                uint32_t b0 = __float_as_uint(Vs[kb + tg    ][nf * 8 + g]);
                uint32_t b1 = __float_as_uint(Vs[kb + tg + 4][nf * 8 + g]);
                mma_tf32(o[nf][0], o[nf][1], o[nf][2], o[nf][3],
                         a0, a1, a2, a3, b0, b1);
            }
        }
    }

    float inv0 = 1.0f / l0, inv1 = 1.0f / l1;
    size_t row0 = ((((size_t)(b * NTOK + q0 + rg)) * HEADS + h) << 6);
    size_t row1 = ((((size_t)(b * NTOK + q0 + rg + 8)) * HEADS + h) << 6);
    #pragma unroll
    for (int nf = 0; nf < 8; nf++) {
        int col = nf * 8 + 2 * tg;
        out[row0 + kperm(col)]     = to_tf32(o[nf][0] * inv0);
        out[row0 + kperm(col + 1)] = to_tf32(o[nf][1] * inv0);
        out[row1 + kperm(col)]     = to_tf32(o[nf][2] * inv1);
        out[row1 + kperm(col + 1)] = to_tf32(o[nf][3] * inv1);
    }
}

// ---------------------------------------------------------------------------
// Launch
// ---------------------------------------------------------------------------
extern "C" void kernel_launch(void* const* d_in, const int* in_sizes, int n_in,
                              void* d_out, int out_size)
{
    const float* x    = (const float*)d_in[0];
    const float* c    = (const float*)d_in[1];
    const float* Wq   = (const float*)d_in[2];
    const float* bq   = (const float*)d_in[3];
    const float* Wkv  = (const float*)d_in[4];
    const float* bkv  = (const float*)d_in[5];
    const float* Wo   = (const float*)d_in[6];
    const float* bo   = (const float*)d_in[7];
    const float* W1   = (const float*)d_in[8];
    const float* b1   = (const float*)d_in[9];
    const float* W2   = (const float*)d_in[10];
    const float* b2   = (const float*)d_in[11];
    const float* Wada = (const float*)d_in[12];
    const float* bada = (const float*)d_in[13];
    float* out = (float*)d_out;

    float *mod, *h, *q, *kv, *att, *m1, *wqkv, *wo, *w1, *w2;
    cudaGetSymbolAddress((void**)&mod,  g_mod);
    cudaGetSymbolAddress((void**)&h,    g_h);
    cudaGetSymbolAddress((void**)&q,    g_q);
    cudaGetSymbolAddress((void**)&kv,   g_kv);
    cudaGetSymbolAddress((void**)&att,  g_att);
    cudaGetSymbolAddress((void**)&m1,   g_m1);
    cudaGetSymbolAddress((void**)&wqkv, g_wqkv);
    cudaGetSymbolAddress((void**)&wo,   g_wo);
    cudaGetSymbolAddress((void**)&w1,   g_w1);
    cudaGetSymbolAddress((void**)&w2,   g_w2);

    cudaFuncSetAttribute(attn_mma_kernel,
                         cudaFuncAttributeMaxDynamicSharedMemorySize, ATTN_SMEM_BYTES);
    cudaFuncSetAttribute(mma_gemm_kernel<1, 128>,
                         cudaFuncAttributeMaxDynamicSharedMemorySize, GEMM_SMEM(128));
    cudaFuncSetAttribute(mma_gemm_kernel<2, 64>,
                         cudaFuncAttributeMaxDynamicSharedMemorySize, GEMM_SMEM(64));
    cudaFuncSetAttribute(mma_gemm_kernel<3, 128>,
                         cudaFuncAttributeMaxDynamicSharedMemorySize, GEMM_SMEM(128));

    // 0) round + row-permute all weights (one launch)
    round_weights_kernel<<<dim3(DMODEL * MLPD / 4 / 256, 5), 256>>>(
        (const float4*)Wq, (const float4*)Wkv, (const float4*)Wo,
        (const float4*)W1, (const float4*)W2,
        (float4*)wqkv, (float4*)wo, (float4*)w1, (float4*)w2);

    // 1) adaLN modulation
    ada_mod_kernel<<<dim3(SIXD / 256, BATCH), 256>>>(c, Wada, bada, mod);

    // 2) h = tf32(modulate(LN(x), sh_msa, sc_msa)), K-permuted
    ln_mod_kernel<<<ROWS, 256>>>(x, mod, 0 * DMODEL, 1 * DMODEL, h);

    // 3) fused QKV GEMM: [q | kv] = h @ [Wq | Wkv] + [bq | bkv]  (natural out)
    mma_gemm_kernel<3, 128><<<dim3(3 * DMODEL / 128, ROWS / 128), 256, GEMM_SMEM(128)>>>(
        h, wqkv, bq, bkv, nullptr, nullptr, q, kv, ROWS, 3 * DMODEL, DMODEL);

    // 4) attention (tensor-core flash; K-permuted att out)
    attn_mma_kernel<<<dim3(NTOK / 128, BATCH * HEADS), 256, ATTN_SMEM_BYTES>>>(q, kv, att);

    // 5) x1 = x + g_msa * (att @ Wo + bo)   -> d_out  (BN=64: 512 blocks)
    mma_gemm_kernel<2, 64><<<dim3(DMODEL / 64, ROWS / 128), 256, GEMM_SMEM(64)>>>(
        att, wo, bo, nullptr, x, mod + 2 * DMODEL, out, nullptr, ROWS, DMODEL, DMODEL);

    // 6) h2 = tf32(modulate(LN(x1), sh_mlp, sc_mlp)), K-permuted
    ln_mod_kernel<<<ROWS, 256>>>(out, mod, 3 * DMODEL, 4 * DMODEL, h);

    // 7) m1 = tf32(gelu(h2 @ W1 + b1)), K-permuted store
    mma_gemm_kernel<1, 128><<<dim3(MLPD / 128, ROWS / 128), 256, GEMM_SMEM(128)>>>(
        h, w1, b1, nullptr, nullptr, nullptr, m1, nullptr, ROWS, MLPD, DMODEL);

    // 8) x2 = x1 + g_mlp * (m1 @ W2 + b2)   -> d_out  (BN=64: 512 blocks)
    mma_gemm_kernel<2, 64><<<dim3(DMODEL / 64, ROWS / 128), 256, GEMM_SMEM(64)>>>(
        m1, w2, b2, nullptr, out, mod + 5 * DMODEL, out, nullptr, ROWS, DMODEL, MLPD);
}

// round 15
// speedup vs baseline: 1.0839x; 1.0839x over previous
#include <cuda_runtime.h>
#include <math.h>
#include <stdint.h>

// ---------------------------------------------------------------------------
// Problem constants
// ---------------------------------------------------------------------------
#define BATCH  4
#define NTOK   1024
#define DMODEL 1024
#define HEADS  16
#define HDIM   64
#define ROWS   (BATCH * NTOK)     // 4096
#define MLPD   4096
#define SIXD   (6 * DMODEL)       // 6144
#define EPS    1e-6f

// ---------------------------------------------------------------------------
// Scratch (device globals: no allocations allowed)
// ---------------------------------------------------------------------------
__device__ float g_mod[BATCH * SIXD];
__device__ float g_h  [ROWS * DMODEL];      // K-permuted (GEMM A operand)
__device__ float g_q  [ROWS * DMODEL];      // natural (attention input)
__device__ float g_kv [ROWS * 2 * DMODEL];  // natural (attention input)
__device__ float g_att[ROWS * DMODEL];      // K-permuted (Wo A operand)
__device__ float g_m1 [ROWS * MLPD];        // K-permuted (W2 A operand)
// tf32-rounded, row-permuted weights; Wq|Wkv fused into [1024][3072]
__device__ float g_wqkv[DMODEL * 3 * DMODEL];
__device__ float g_wo  [DMODEL * DMODEL];
__device__ float g_w1  [DMODEL * MLPD];
__device__ float g_w2  [MLPD * DMODEL];

// ---------------------------------------------------------------------------
// Helpers
// ---------------------------------------------------------------------------
// K-dim permutation within each group of 8: j -> 2j (j<4), 2j-7 (j>=4).
// Makes mma fragment pair (k=tg, k=tg+4) adjacent in storage -> LDS.64.
__device__ __forceinline__ int kperm(int k) {
    return (k & ~7) | (((k & 3) << 1) | ((k >> 2) & 1));
}

__device__ __forceinline__ float gelu_tanh(float y) {
    float y3 = y * y * y;
    return 0.5f * y * (1.0f + tanhf(0.7978845608028654f * (y + 0.044715f * y3)));
}

__device__ __forceinline__ float to_tf32(float x) {
    uint32_t y;
    asm("cvt.rna.tf32.f32 %0, %1;" : "=r"(y) : "f"(x));
    return __uint_as_float(y);
}

__device__ __forceinline__ void cp_async16(void* smem_dst, const void* gmem_src) {
    uint32_t s = (uint32_t)__cvta_generic_to_shared(smem_dst);
    asm volatile("cp.async.cg.shared.global [%0], [%1], 16;\n"
                 :: "r"(s), "l"(gmem_src));
}
__device__ __forceinline__ void cp_commit() {
    asm volatile("cp.async.commit_group;\n");
}
template <int N>
__device__ __forceinline__ void cp_wait() {
    asm volatile("cp.async.wait_group %0;\n" :: "n"(N));
}

__device__ __forceinline__ void mma_tf32(
    float& d0, float& d1, float& d2, float& d3,
    uint32_t a0, uint32_t a1, uint32_t a2, uint32_t a3,
    uint32_t b0, uint32_t b1)
{
    asm volatile(
        "mma.sync.aligned.m16n8k8.row.col.f32.tf32.tf32.f32 "
        "{%0,%1,%2,%3}, {%4,%5,%6,%7}, {%8,%9}, {%0,%1,%2,%3};"
        : "+f"(d0), "+f"(d1), "+f"(d2), "+f"(d3)
        : "r"(a0), "r"(a1), "r"(a2), "r"(a3), "r"(b0), "r"(b1));
}

// ---------------------------------------------------------------------------
// Kernel 0: round ALL weights to tf32 + permute K-dim rows, one launch.
// ---------------------------------------------------------------------------
__global__ void __launch_bounds__(256) round_weights_kernel(
    const float4* __restrict__ Wq, const float4* __restrict__ Wkv,
    const float4* __restrict__ Wo, const float4* __restrict__ W1,
    const float4* __restrict__ W2,
    float4* __restrict__ wqkv, float4* __restrict__ wo,
    float4* __restrict__ w1, float4* __restrict__ w2)
{
    const int t = blockIdx.y;
    const int i = blockIdx.x * 256 + threadIdx.x;
    const float4* src = nullptr;
    float4* dst = nullptr;
    int n4 = 0, di = 0;
    switch (t) {
        case 0: n4 = DMODEL * DMODEL / 4;     src = Wq;  dst = wqkv;
                di = kperm(i >> 8) * 768 + (i & 255); break;
        case 1: n4 = DMODEL * 2 * DMODEL / 4; src = Wkv; dst = wqkv;
                di = kperm(i >> 9) * 768 + 256 + (i & 511); break;
        case 2: n4 = DMODEL * DMODEL / 4;     src = Wo;  dst = wo;
                di = kperm(i >> 8) * 256 + (i & 255); break;
        case 3: n4 = DMODEL * MLPD / 4;       src = W1;  dst = w1;
                di = kperm(i >> 10) * 1024 + (i & 1023); break;
        case 4: n4 = MLPD * DMODEL / 4;       src = W2;  dst = w2;
                di = kperm(i >> 8) * 256 + (i & 255); break;
    }
    if (i < n4) {
        float4 v = src[i];
        v.x = to_tf32(v.x); v.y = to_tf32(v.y);
        v.z = to_tf32(v.z); v.w = to_tf32(v.w);
        dst[di] = v;
    }
}

// ---------------------------------------------------------------------------
// Kernel 1: mod = silu(c) @ Wada + bada        [4, 6144]
// ---------------------------------------------------------------------------
__global__ void __launch_bounds__(256) ada_mod_kernel(
    const float* __restrict__ c, const float* __restrict__ Wada,
    const float* __restrict__ bada, float* __restrict__ mod)
{
    __shared__ float sc[DMODEL];
    int b = blockIdx.y;
    int n = blockIdx.x * 256 + threadIdx.x;
    for (int i = threadIdx.x; i < DMODEL; i += 256) {
        float v = c[b * DMODEL + i];
        sc[i] = v / (1.0f + __expf(-v));
    }
    __syncthreads();
    float acc = 0.0f;
    const float* wp = Wada + n;
    for (int k = 0; k < DMODEL; k++)
        acc = fmaf(sc[k], wp[(size_t)k * SIXD], acc);
    mod[b * SIXD + n] = acc + bada[n];
}

// ---------------------------------------------------------------------------
// Kernel 2: out = tf32(LN(x) * (1 + scale) + shift), K-permuted store
// ---------------------------------------------------------------------------
__global__ void __launch_bounds__(256) ln_mod_kernel(
    const float* __restrict__ x, const float* __restrict__ mod,
    int shiftOff, int scaleOff, float* __restrict__ out)
{
    __shared__ float red[8];
    int row = blockIdx.x;
    int b = row >> 10;
    const float4* xr = (const float4*)(x + (size_t)row * DMODEL);
    float4 v = xr[threadIdx.x];

    float s = v.x + v.y + v.z + v.w;
    #pragma unroll
    for (int o = 16; o; o >>= 1) s += __shfl_xor_sync(0xffffffffu, s, o);
    if ((threadIdx.x & 31) == 0) red[threadIdx.x >> 5] = s;
    __syncthreads();
    float tot = 0.f;
    #pragma unroll
    for (int w = 0; w < 8; w++) tot += red[w];
    float mean = tot * (1.0f / DMODEL);
    __syncthreads();

    float dx = v.x - mean, dy = v.y - mean, dz = v.z - mean, dw = v.w - mean;
    float q = dx * dx + dy * dy + dz * dz + dw * dw;
    #pragma unroll
    for (int o = 16; o; o >>= 1) q += __shfl_xor_sync(0xffffffffu, q, o);
    if ((threadIdx.x & 31) == 0) red[threadIdx.x >> 5] = q;
    __syncthreads();
    float vtot = 0.f;
    #pragma unroll
    for (int w = 0; w < 8; w++) vtot += red[w];
    float rstd = rsqrtf(vtot * (1.0f / DMODEL) + EPS);

    int c0 = threadIdx.x * 4;
    const float* base = mod + (size_t)b * SIXD;
    float4 shv = *(const float4*)(base + shiftOff + c0);
    float4 scv = *(const float4*)(base + scaleOff + c0);
    float* orow = out + (size_t)row * DMODEL;
    orow[kperm(c0 + 0)] = to_tf32(dx * rstd * (1.0f + scv.x) + shv.x);
    orow[kperm(c0 + 1)] = to_tf32(dy * rstd * (1.0f + scv.y) + shv.y);
    orow[kperm(c0 + 2)] = to_tf32(dz * rstd * (1.0f + scv.z) + shv.z);
    orow[kperm(c0 + 3)] = to_tf32(dw * rstd * (1.0f + scv.w) + shv.w);
}

// ---------------------------------------------------------------------------
// Kernel 3: TF32 mma.sync GEMM, cp.async 3-stage pipeline, ONE sync/tile.
// 8 warps, warp tile 64x32 (R9 optimum). A/B K-permuted within groups of 8
// (A fragments load as LDS.64).
//   EPI 1: C = tf32(gelu(acc + bias[n])), K-permuted store (feeds W2)
//   EPI 2: C = res + gate * (acc + bias[n])   (natural; exact fp32 residual)
//   EPI 3: qkv split (natural): cols<1024 -> C (+bias), else -> C2 (+bias2)
// ---------------------------------------------------------------------------
#define GSTAGES 3
#define APAD 40
#define BPAD 132
#define GEMM_SMEM_BYTES (GSTAGES * (128 * APAD + 32 * BPAD) * (int)sizeof(float))

template <int EPI>
__global__ void __launch_bounds__(256, 2) mma_gemm_kernel(
    const float* __restrict__ A, const float* __restrict__ B,
    const float* __restrict__ bias, const float* __restrict__ bias2,
    const float* __restrict__ res, const float* __restrict__ gate,
    float* __restrict__ C, float* __restrict__ C2,
    int M, int N, int K)
{
    extern __shared__ char smemRaw[];
    float (*As)[128][APAD] = reinterpret_cast<float(*)[128][APAD]>(smemRaw);
    float (*Bs)[32][BPAD]  = reinterpret_cast<float(*)[32][BPAD]>(
        smemRaw + GSTAGES * 128 * APAD * sizeof(float));

    const int tid  = threadIdx.x;
    const int lane = tid & 31;
    const int warp = tid >> 5;
    const int wm   = warp & 1;
    const int wn   = warp >> 1;
    const int bm   = blockIdx.y * 128;
    const int bn   = blockIdx.x * 128;

    const int g  = lane >> 2;
    const int tg = lane & 3;

    const int aRow0 = tid >> 3;
    const int aK4   = (tid & 7) * 4;
    const int bK0   = tid >> 5;
    const int bN4   = (tid & 31) * 4;

    float acc[4][4][4];
    #pragma unroll
    for (int i = 0; i < 4; i++)
        #pragma unroll
        for (int j = 0; j < 4; j++)
            #pragma unroll
            for (int r = 0; r < 4; r++) acc[i][j][r] = 0.f;

    const int kTiles = K >> 5;

    auto load_tile = [&](int st, int k0) {
        #pragma unroll
        for (int i = 0; i < 4; i++) {
            int r = i * 32 + aRow0;
            cp_async16(&As[st][r][aK4], A + (size_t)(bm + r) * K + k0 + aK4);
        }
        #pragma unroll
        for (int i = 0; i < 4; i++) {
            int kk = i * 8 + bK0;
            cp_async16(&Bs[st][kk][bN4], B + (size_t)(k0 + kk) * N + bn + bN4);
        }
    };

    #pragma unroll
    for (int s = 0; s < GSTAGES - 1; s++) {
        load_tile(s, s * 32);
        cp_commit();
    }

    for (int it = 0; it < kTiles; it++) {
        cp_wait<GSTAGES - 2>();
        __syncthreads();

        int nxt = it + GSTAGES - 1;
        if (nxt < kTiles)
            load_tile(nxt % GSTAGES, nxt * 32);
        cp_commit();

        const int st = it % GSTAGES;
        #pragma unroll
        for (int ks = 0; ks < 4; ks++) {
            const int kb = ks * 8;
            uint32_t a[4][4], b[4][2];
            #pragma unroll
            for (int mf = 0; mf < 4; mf++) {
                int r = wm * 64 + mf * 16 + g;
                float2 av0 = *(const float2*)&As[st][r    ][kb + 2 * tg];
                float2 av1 = *(const float2*)&As[st][r + 8][kb + 2 * tg];
                a[mf][0] = __float_as_uint(av0.x);
                a[mf][1] = __float_as_uint(av1.x);
                a[mf][2] = __float_as_uint(av0.y);
                a[mf][3] = __float_as_uint(av1.y);
            }
            #pragma unroll
            for (int nf = 0; nf < 4; nf++) {
                int n = wn * 32 + nf * 8 + g;
                b[nf][0] = __float_as_uint(Bs[st][kb + 2 * tg    ][n]);
                b[nf][1] = __float_as_uint(Bs[st][kb + 2 * tg + 1][n]);
            }
            #pragma unroll
            for (int mf = 0; mf < 4; mf++)
                #pragma unroll
                for (int nf = 0; nf < 4; nf++)
                    mma_tf32(acc[mf][nf][0], acc[mf][nf][1],
                             acc[mf][nf][2], acc[mf][nf][3],
                             a[mf][0], a[mf][1], a[mf][2], a[mf][3],
                             b[nf][0], b[nf][1]);
        }
    }

    #pragma unroll
    for (int mf = 0; mf < 4; mf++) {
        #pragma unroll
        for (int half = 0; half < 2; half++) {
            int row = bm + wm * 64 + mf * 16 + g + half * 8;
            size_t gbase = (size_t)(row >> 10) * SIXD;
            #pragma unroll
            for (int nf = 0; nf < 4; nf++) {
                int col = bn + wn * 32 + nf * 8 + 2 * tg;
                float y0 = acc[mf][nf][half * 2 + 0];
                float y1 = acc[mf][nf][half * 2 + 1];
                if (EPI == 3) {
                    if (col < DMODEL) {
                        size_t rb = (size_t)row * DMODEL;
                        C[rb + col]     = to_tf32(y0 + bias[col]);
                        C[rb + col + 1] = to_tf32(y1 + bias[col + 1]);
                    } else {
                        int c2 = col - DMODEL;
                        size_t rb = (size_t)row * (2 * DMODEL);
                        C2[rb + c2]     = to_tf32(y0 + bias2[c2]);
                        C2[rb + c2 + 1] = to_tf32(y1 + bias2[c2 + 1]);
                    }
                } else if (EPI == 1) {
                    size_t rbase = (size_t)row * N;
                    C[rbase + kperm(col)]     = to_tf32(gelu_tanh(y0 + bias[col]));
                    C[rbase + kperm(col + 1)] = to_tf32(gelu_tanh(y1 + bias[col + 1]));
                } else {
                    size_t rbase = (size_t)row * N;
                    y0 = res[rbase + col]     + gate[gbase + col]     * (y0 + bias[col]);
                    y1 = res[rbase + col + 1] + gate[gbase + col + 1] * (y1 + bias[col + 1]);
                    C[rbase + col]     = y0;
                    C[rbase + col + 1] = y1;
                }
            }
        }
    }
}

// ---------------------------------------------------------------------------
// Kernel 4: flash attention on tf32 tensor cores
// 8 warps x m16 = 128 q rows per block, Bc=64, d=64.
// K/V for tile jt+1 prefetched into registers during tile jt's PV compute
// (issued where s[] regs are dead), stored to smem at top of next iter.
// Output store is K-permuted (att feeds the Wo GEMM as A).
// ---------------------------------------------------------------------------
#define AQ_PAD 68
#define AK_PAD 68
#define AV_PAD 72
#define AP_PAD 68
#define ATTN_SMEM_BYTES ((128 * AQ_PAD + 64 * AK_PAD + 64 * AV_PAD + 128 * AP_PAD) * (int)sizeof(float))

__global__ void __launch_bounds__(256, 2) attn_mma_kernel(
    const float* __restrict__ q, const float* __restrict__ kv,
    float* __restrict__ out)
{
    extern __shared__ float sm[];
    float (*Qs)[AQ_PAD] = reinterpret_cast<float(*)[AQ_PAD]>(sm);
    float (*Ks)[AK_PAD] = reinterpret_cast<float(*)[AK_PAD]>(sm + 128 * AQ_PAD);
    float (*Vs)[AV_PAD] = reinterpret_cast<float(*)[AV_PAD]>(sm + 128 * AQ_PAD + 64 * AK_PAD);
    float (*Ps)[AP_PAD] = reinterpret_cast<float(*)[AP_PAD]>(sm + 128 * AQ_PAD + 64 * AK_PAD + 64 * AV_PAD);

    const int tid  = threadIdx.x;
    const int lane = tid & 31;
    const int warp = tid >> 5;
    const int g    = lane >> 2;
    const int tg   = lane & 3;
    const int b    = blockIdx.y >> 4;
    const int h    = blockIdx.y & 15;
    const int q0   = blockIdx.x * 128;
    const int rg   = warp * 16 + g;

    // this thread's 4 (row, d4) slots for K/V staging
    const int kvRow[4] = { tid >> 4, (tid + 256) >> 4, (tid + 512) >> 4, (tid + 768) >> 4 };
    const int kvD4 = (tid & 15) * 4;

    for (int t = tid; t < 128 * 16; t += 256) {
        int r = t >> 4, d4 = (t & 15) * 4;
        float4 v = *(const float4*)(q +
            ((((size_t)(b * NTOK + q0 + r)) * HEADS + h) << 6) + d4);
        Qs[r][d4 + 0] = v.x * 0.125f; Qs[r][d4 + 1] = v.y * 0.125f;
        Qs[r][d4 + 2] = v.z * 0.125f; Qs[r][d4 + 3] = v.w * 0.125f;
    }

    float o[8][4];
    #pragma unroll
    for (int nf = 0; nf < 8; nf++)
        #pragma unroll
        for (int r = 0; r < 4; r++) o[nf][r] = 0.f;
    float m0 = -INFINITY, m1 = -INFINITY, l0 = 0.f, l1 = 0.f;

    // prologue: prefetch jt=0 K/V into registers
    float4 kreg[4], vreg[4];
    #pragma unroll
    for (int i = 0; i < 4; i++) {
        size_t base = (size_t)(b * NTOK + kvRow[i]) * (2 * DMODEL) + h * HDIM + kvD4;
        kreg[i] = *(const float4*)(kv + base);
        vreg[i] = *(const float4*)(kv + base + DMODEL);
    }

    for (int jt = 0; jt < NTOK / 64; jt++) {
        __syncthreads();   // WAR: previous iter's reads of Ks/Vs done
        #pragma unroll
        for (int i = 0; i < 4; i++) {
            int r = kvRow[i];
            Ks[r][kvD4 + 0] = kreg[i].x; Ks[r][kvD4 + 1] = kreg[i].y;
            Ks[r][kvD4 + 2] = kreg[i].z; Ks[r][kvD4 + 3] = kreg[i].w;
            Vs[r][kvD4 + 0] = vreg[i].x; Vs[r][kvD4 + 1] = vreg[i].y;
            Vs[r][kvD4 + 2] = vreg[i].z; Vs[r][kvD4 + 3] = vreg[i].w;
        }
        __syncthreads();

        float s[8][4];
        #pragma unroll
        for (int nf = 0; nf < 8; nf++)
            #pragma unroll
            for (int r = 0; r < 4; r++) s[nf][r] = 0.f;
        #pragma unroll
        for (int kb = 0; kb < 64; kb += 8) {
            uint32_t a0 = __float_as_uint(Qs[rg    ][kb + tg    ]);
            uint32_t a1 = __float_as_uint(Qs[rg + 8][kb + tg    ]);
            uint32_t a2 = __float_as_uint(Qs[rg    ][kb + tg + 4]);
            uint32_t a3 = __float_as_uint(Qs[rg + 8][kb + tg + 4]);
            #pragma unroll
            for (int nf = 0; nf < 8; nf++) {
                uint32_t b0 = __float_as_uint(Ks[nf * 8 + g][kb + tg    ]);
                uint32_t b1 = __float_as_uint(Ks[nf * 8 + g][kb + tg + 4]);
                mma_tf32(s[nf][0], s[nf][1], s[nf][2], s[nf][3],
                         a0, a1, a2, a3, b0, b1);
            }
        }

        float mx0 = -INFINITY, mx1 = -INFINITY;
        #pragma unroll
        for (int nf = 0; nf < 8; nf++) {
            mx0 = fmaxf(mx0, fmaxf(s[nf][0], s[nf][1]));
            mx1 = fmaxf(mx1, fmaxf(s[nf][2], s[nf][3]));
        }
        mx0 = fmaxf(mx0, __shfl_xor_sync(0xffffffffu, mx0, 1));
        mx0 = fmaxf(mx0, __shfl_xor_sync(0xffffffffu, mx0, 2));
        mx1 = fmaxf(mx1, __shfl_xor_sync(0xffffffffu, mx1, 1));
        mx1 = fmaxf(mx1, __shfl_xor_sync(0xffffffffu, mx1, 2));
        float mN0 = fmaxf(m0, mx0), mN1 = fmaxf(m1, mx1);
        float c0 = __expf(m0 - mN0), c1 = __expf(m1 - mN1);
        float sum0 = 0.f, sum1 = 0.f;
        #pragma unroll
        for (int nf = 0; nf < 8; nf++) {
            s[nf][0] = __expf(s[nf][0] - mN0); sum0 += s[nf][0];
            s[nf][1] = __expf(s[nf][1] - mN0); sum0 += s[nf][1];
            s[nf][2] = __expf(s[nf][2] - mN1); sum1 += s[nf][2];
            s[nf][3] = __expf(s[nf][3] - mN1); sum1 += s[nf][3];
        }
        sum0 += __shfl_xor_sync(0xffffffffu, sum0, 1);
        sum0 += __shfl_xor_sync(0xffffffffu, sum0, 2);
        sum1 += __shfl_xor_sync(0xffffffffu, sum1, 1);
        sum1 += __shfl_xor_sync(0xffffffffu, sum1, 2);
        l0 = l0 * c0 + sum0; l1 = l1 * c1 + sum1;
        m0 = mN0; m1 = mN1;
        #pragma unroll
        for (int nf = 0; nf < 8; nf++) {
            o[nf][0] *= c0; o[nf][1] *= c0;
            o[nf][2] *= c1; o[nf][3] *= c1;
        }

        #pragma unroll
        for (int nf = 0; nf < 8; nf++) {
            int col = nf * 8 + 2 * tg;
            Ps[rg    ][col] = to_tf32(s[nf][0]); Ps[rg    ][col + 1] = to_tf32(s[nf][1]);
            Ps[rg + 8][col] = to_tf32(s[nf][2]); Ps[rg + 8][col + 1] = to_tf32(s[nf][3]);
        }
        __syncwarp();

        // prefetch next tile's K/V while s[] is dead; latency hidden by PV mma
        if (jt + 1 < NTOK / 64) {
            int j0n = (jt + 1) * 64;
            #pragma unroll
            for (int i = 0; i < 4; i++) {
                size_t base = (size_t)(b * NTOK + j0n + kvRow[i]) * (2 * DMODEL)
                            + h * HDIM + kvD4;
                kreg[i] = *(const float4*)(kv + base);
                vreg[i] = *(const float4*)(kv + base + DMODEL);
            }
        }

        #pragma unroll
        for (int kb = 0; kb < 64; kb += 8) {
            uint32_t a0 = __float_as_uint(Ps[rg    ][kb + tg    ]);
            uint32_t a1 = __float_as_uint(Ps[rg + 8][kb + tg    ]);
            uint32_t a2 = __float_as_uint(Ps[rg    ][kb + tg + 4]);
            uint32_t a3 = __float_as_uint(Ps[rg + 8][kb + tg + 4]);
            #pragma unroll
            for (int nf = 0; nf < 8; nf++) {
                uint32_t b0 = __float_as_uint(Vs[kb + tg    ][nf * 8 + g]);
                uint32_t b1 = __float_as_uint(Vs[kb + tg + 4][nf * 8 + g]);
                mma_tf32(o[nf][0], o[nf][1], o[nf][2], o[nf][3],
                         a0, a1, a2, a3, b0, b1);
            }
        }
    }

    float inv0 = 1.0f / l0, inv1 = 1.0f / l1;
    size_t row0 = ((((size_t)(b * NTOK + q0 + rg)) * HEADS + h) << 6);
    size_t row1 = ((((size_t)(b * NTOK + q0 + rg + 8)) * HEADS + h) << 6);
    #pragma unroll
    for (int nf = 0; nf < 8; nf++) {
        int col = nf * 8 + 2 * tg;
        out[row0 + kperm(col)]     = to_tf32(o[nf][0] * inv0);
        out[row0 + kperm(col + 1)] = to_tf32(o[nf][1] * inv0);
        out[row1 + kperm(col)]     = to_tf32(o[nf][2] * inv1);
        out[row1 + kperm(col + 1)] = to_tf32(o[nf][3] * inv1);
    }
}

// ---------------------------------------------------------------------------
// Launch
// ---------------------------------------------------------------------------
extern "C" void kernel_launch(void* const* d_in, const int* in_sizes, int n_in,
                              void* d_out, int out_size)
{
    const float* x    = (const float*)d_in[0];
    const float* c    = (const float*)d_in[1];
    const float* Wq   = (const float*)d_in[2];
    const float* bq   = (const float*)d_in[3];
    const float* Wkv  = (const float*)d_in[4];
    const float* bkv  = (const float*)d_in[5];
    const float* Wo   = (const float*)d_in[6];
    const float* bo   = (const float*)d_in[7];
    const float* W1   = (const float*)d_in[8];
    const float* b1   = (const float*)d_in[9];
    const float* W2   = (const float*)d_in[10];
    const float* b2   = (const float*)d_in[11];
    const float* Wada = (const float*)d_in[12];
    const float* bada = (const float*)d_in[13];
    float* out = (float*)d_out;

    float *mod, *h, *q, *kv, *att, *m1, *wqkv, *wo, *w1, *w2;
    cudaGetSymbolAddress((void**)&mod,  g_mod);
    cudaGetSymbolAddress((void**)&h,    g_h);
    cudaGetSymbolAddress((void**)&q,    g_q);
    cudaGetSymbolAddress((void**)&kv,   g_kv);
    cudaGetSymbolAddress((void**)&att,  g_att);
    cudaGetSymbolAddress((void**)&m1,   g_m1);
    cudaGetSymbolAddress((void**)&wqkv, g_wqkv);
    cudaGetSymbolAddress((void**)&wo,   g_wo);
    cudaGetSymbolAddress((void**)&w1,   g_w1);
    cudaGetSymbolAddress((void**)&w2,   g_w2);

    cudaFuncSetAttribute(attn_mma_kernel,
                         cudaFuncAttributeMaxDynamicSharedMemorySize, ATTN_SMEM_BYTES);
    cudaFuncSetAttribute(mma_gemm_kernel<1>,
                         cudaFuncAttributeMaxDynamicSharedMemorySize, GEMM_SMEM_BYTES);
    cudaFuncSetAttribute(mma_gemm_kernel<2>,
                         cudaFuncAttributeMaxDynamicSharedMemorySize, GEMM_SMEM_BYTES);
    cudaFuncSetAttribute(mma_gemm_kernel<3>,
                         cudaFuncAttributeMaxDynamicSharedMemorySize, GEMM_SMEM_BYTES);

    // 0) round + row-permute all weights (one launch)
    round_weights_kernel<<<dim3(DMODEL * MLPD / 4 / 256, 5), 256>>>(
        (const float4*)Wq, (const float4*)Wkv, (const float4*)Wo,
        (const float4*)W1, (const float4*)W2,
        (float4*)wqkv, (float4*)wo, (float4*)w1, (float4*)w2);

    // 1) adaLN modulation
    ada_mod_kernel<<<dim3(SIXD / 256, BATCH), 256>>>(c, Wada, bada, mod);

    // 2) h = tf32(modulate(LN(x), sh_msa, sc_msa)), K-permuted
    ln_mod_kernel<<<ROWS, 256>>>(x, mod, 0 * DMODEL, 1 * DMODEL, h);

    // 3) fused QKV GEMM: [q | kv] = h @ [Wq | Wkv] + [bq | bkv]  (natural out)
    mma_gemm_kernel<3><<<dim3(3 * DMODEL / 128, ROWS / 128), 256, GEMM_SMEM_BYTES>>>(
        h, wqkv, bq, bkv, nullptr, nullptr, q, kv, ROWS, 3 * DMODEL, DMODEL);

    // 4) attention (tensor-core flash; K-permuted att out)
    attn_mma_kernel<<<dim3(NTOK / 128, BATCH * HEADS), 256, ATTN_SMEM_BYTES>>>(q, kv, att);

    // 5) x1 = x + g_msa * (att @ Wo + bo)   -> d_out (natural)
    mma_gemm_kernel<2><<<dim3(DMODEL / 128, ROWS / 128), 256, GEMM_SMEM_BYTES>>>(
        att, wo, bo, nullptr, x, mod + 2 * DMODEL, out, nullptr, ROWS, DMODEL, DMODEL);

    // 6) h2 = tf32(modulate(LN(x1), sh_mlp, sc_mlp)), K-permuted
    ln_mod_kernel<<<ROWS, 256>>>(out, mod, 3 * DMODEL, 4 * DMODEL, h);

    // 7) m1 = tf32(gelu(h2 @ W1 + b1)), K-permuted store
    mma_gemm_kernel<1><<<dim3(MLPD / 128, ROWS / 128), 256, GEMM_SMEM_BYTES>>>(
        h, w1, b1, nullptr, nullptr, nullptr, m1, nullptr, ROWS, MLPD, DMODEL);

    // 8) x2 = x1 + g_mlp * (m1 @ W2 + b2)   -> d_out (natural)
    mma_gemm_kernel<2><<<dim3(DMODEL / 128, ROWS / 128), 256, GEMM_SMEM_BYTES>>>(
        m1, w2, b2, nullptr, out, mod + 5 * DMODEL, out, nullptr, ROWS, DMODEL, MLPD);
}

// round 16
// speedup vs baseline: 1.5654x; 1.4442x over previous
#include <cuda_runtime.h>
#include <cuda_fp16.h>
#include <math.h>
#include <stdint.h>

// ---------------------------------------------------------------------------
// Problem constants
// ---------------------------------------------------------------------------
#define BATCH  4
#define NTOK   1024
#define DMODEL 1024
#define HEADS  16
#define HDIM   64
#define ROWS   (BATCH * NTOK)     // 4096
#define MLPD   4096
#define SIXD   (6 * DMODEL)       // 6144
#define EPS    1e-6f

// ---------------------------------------------------------------------------
// Scratch (device globals: no allocations allowed)
// ---------------------------------------------------------------------------
__device__ float  g_mod[BATCH * SIXD];
__device__ __half g_h  [ROWS * DMODEL];      // fp16 (GEMM A operand)
__device__ float  g_q  [ROWS * DMODEL];      // fp32 (attention input)
__device__ float  g_kv [ROWS * 2 * DMODEL];  // fp32 (attention input)
__device__ __half g_att[ROWS * DMODEL];      // fp16 (Wo A operand)
__device__ __half g_m1 [ROWS * MLPD];        // fp16 (W2 A operand)
// fp16, TRANSPOSED weights [N][K]; Wq|Wkv stacked into [3072][1024]
__device__ __half g_wqkv[3 * DMODEL * DMODEL];
__device__ __half g_wo  [DMODEL * DMODEL];
__device__ __half g_w1  [MLPD * DMODEL];
__device__ __half g_w2  [DMODEL * MLPD];

// ---------------------------------------------------------------------------
// Helpers
// ---------------------------------------------------------------------------
__device__ __forceinline__ float gelu_tanh(float y) {
    float y3 = y * y * y;
    return 0.5f * y * (1.0f + tanhf(0.7978845608028654f * (y + 0.044715f * y3)));
}

__device__ __forceinline__ float to_tf32(float x) {
    uint32_t y;
    asm("cvt.rna.tf32.f32 %0, %1;" : "=r"(y) : "f"(x));
    return __uint_as_float(y);
}

__device__ __forceinline__ void cp_async16(void* smem_dst, const void* gmem_src) {
    uint32_t s = (uint32_t)__cvta_generic_to_shared(smem_dst);
    asm volatile("cp.async.cg.shared.global [%0], [%1], 16;\n"
                 :: "r"(s), "l"(gmem_src));
}
__device__ __forceinline__ void cp_commit() {
    asm volatile("cp.async.commit_group;\n");
}
template <int N>
__device__ __forceinline__ void cp_wait() {
    asm volatile("cp.async.wait_group %0;\n" :: "n"(N));
}

// tf32 mma (attention only)
__device__ __forceinline__ void mma_tf32(
    float& d0, float& d1, float& d2, float& d3,
    uint32_t a0, uint32_t a1, uint32_t a2, uint32_t a3,
    uint32_t b0, uint32_t b1)
{
    asm volatile(
        "mma.sync.aligned.m16n8k8.row.col.f32.tf32.tf32.f32 "
        "{%0,%1,%2,%3}, {%4,%5,%6,%7}, {%8,%9}, {%0,%1,%2,%3};"
        : "+f"(d0), "+f"(d1), "+f"(d2), "+f"(d3)
        : "r"(a0), "r"(a1), "r"(a2), "r"(a3), "r"(b0), "r"(b1));
}

// fp16 mma, fp32 accumulate (GEMMs)
__device__ __forceinline__ void mma_f16(
    float& d0, float& d1, float& d2, float& d3,
    uint32_t a0, uint32_t a1, uint32_t a2, uint32_t a3,
    uint32_t b0, uint32_t b1)
{
    asm volatile(
        "mma.sync.aligned.m16n8k16.row.col.f32.f16.f16.f32 "
        "{%0,%1,%2,%3}, {%4,%5,%6,%7}, {%8,%9}, {%0,%1,%2,%3};"
        : "+f"(d0), "+f"(d1), "+f"(d2), "+f"(d3)
        : "r"(a0), "r"(a1), "r"(a2), "r"(a3), "r"(b0), "r"(b1));
}

__device__ __forceinline__ void ldsm_x4(uint32_t* r, uint32_t addr) {
    asm volatile("ldmatrix.sync.aligned.m8n8.x4.shared.b16 {%0,%1,%2,%3}, [%4];"
                 : "=r"(r[0]), "=r"(r[1]), "=r"(r[2]), "=r"(r[3]) : "r"(addr));
}
__device__ __forceinline__ void ldsm_x2(uint32_t* r, uint32_t addr) {
    asm volatile("ldmatrix.sync.aligned.m8n8.x2.shared.b16 {%0,%1}, [%2];"
                 : "=r"(r[0]), "=r"(r[1]) : "r"(addr));
}

// ---------------------------------------------------------------------------
// Kernel 0: transpose + fp16-convert weights: src fp32 [K][N] -> dst half [N][K]
// grid (4096, 5), block (32, 8); 32x32 tiles through padded smem.
// ---------------------------------------------------------------------------
__global__ void __launch_bounds__(256) transpose_half_kernel(
    const float* __restrict__ Wq, const float* __restrict__ Wkv,
    const float* __restrict__ Wo, const float* __restrict__ W1,
    const float* __restrict__ W2,
    __half* __restrict__ wqkvT, __half* __restrict__ woT,
    __half* __restrict__ w1T, __half* __restrict__ w2T)
{
    __shared__ float s[32][33];
    const int t = blockIdx.y;
    const int i = blockIdx.x;
    const float* src = nullptr;
    __half* dst = nullptr;
    int K = 0, N = 0, rowOff = 0;
    switch (t) {
        case 0: src = Wq;  dst = wqkvT; K = 1024; N = 1024; rowOff = 0;    break;
        case 1: src = Wkv; dst = wqkvT; K = 1024; N = 2048; rowOff = 1024; break;
        case 2: src = Wo;  dst = woT;   K = 1024; N = 1024; rowOff = 0;    break;
        case 3: src = W1;  dst = w1T;   K = 1024; N = 4096; rowOff = 0;    break;
        case 4: src = W2;  dst = w2T;   K = 4096; N = 1024; rowOff = 0;    break;
    }
    const int ntx = N >> 5;
    if (i >= (K >> 5) * ntx) return;
    const int kb = i / ntx, nb = i % ntx;
    const int tx = threadIdx.x, ty = threadIdx.y;

    #pragma unroll
    for (int j = 0; j < 4; j++) {
        int r = ty + j * 8;
        s[r][tx] = src[(size_t)(kb * 32 + r) * N + nb * 32 + tx];
    }
    __syncthreads();
    #pragma unroll
    for (int j = 0; j < 4; j++) {
        int r = ty + j * 8;
        dst[(size_t)(rowOff + nb * 32 + r) * K + kb * 32 + tx] =
            __float2half_rn(s[tx][r]);
    }
}

// ---------------------------------------------------------------------------
// Kernel 1: mod = silu(c) @ Wada + bada        [4, 6144]
// ---------------------------------------------------------------------------
__global__ void __launch_bounds__(256) ada_mod_kernel(
    const float* __restrict__ c, const float* __restrict__ Wada,
    const float* __restrict__ bada, float* __restrict__ mod)
{
    __shared__ float sc[DMODEL];
    int b = blockIdx.y;
    int n = blockIdx.x * 256 + threadIdx.x;
    for (int i = threadIdx.x; i < DMODEL; i += 256) {
        float v = c[b * DMODEL + i];
        sc[i] = v / (1.0f + __expf(-v));
    }
    __syncthreads();
    float acc = 0.0f;
    const float* wp = Wada + n;
    for (int k = 0; k < DMODEL; k++)
        acc = fmaf(sc[k], wp[(size_t)k * SIXD], acc);
    mod[b * SIXD + n] = acc + bada[n];
}

// ---------------------------------------------------------------------------
// Kernel 2: out = fp16(LN(x) * (1 + scale) + shift)
// ---------------------------------------------------------------------------
__global__ void __launch_bounds__(256) ln_mod_kernel(
    const float* __restrict__ x, const float* __restrict__ mod,
    int shiftOff, int scaleOff, __half* __restrict__ out)
{
    __shared__ float red[8];
    int row = blockIdx.x;
    int b = row >> 10;
    const float4* xr = (const float4*)(x + (size_t)row * DMODEL);
    float4 v = xr[threadIdx.x];

    float s = v.x + v.y + v.z + v.w;
    #pragma unroll
    for (int o = 16; o; o >>= 1) s += __shfl_xor_sync(0xffffffffu, s, o);
    if ((threadIdx.x & 31) == 0) red[threadIdx.x >> 5] = s;
    __syncthreads();
    float tot = 0.f;
    #pragma unroll
    for (int w = 0; w < 8; w++) tot += red[w];
    float mean = tot * (1.0f / DMODEL);
    __syncthreads();

    float dx = v.x - mean, dy = v.y - mean, dz = v.z - mean, dw = v.w - mean;
    float q = dx * dx + dy * dy + dz * dz + dw * dw;
    #pragma unroll
    for (int o = 16; o; o >>= 1) q += __shfl_xor_sync(0xffffffffu, q, o);
    if ((threadIdx.x & 31) == 0) red[threadIdx.x >> 5] = q;
    __syncthreads();
    float vtot = 0.f;
    #pragma unroll
    for (int w = 0; w < 8; w++) vtot += red[w];
    float rstd = rsqrtf(vtot * (1.0f / DMODEL) + EPS);

    int c0 = threadIdx.x * 4;
    const float* base = mod + (size_t)b * SIXD;
    float4 shv = *(const float4*)(base + shiftOff + c0);
    float4 scv = *(const float4*)(base + scaleOff + c0);
    __half2* op = (__half2*)(out + (size_t)row * DMODEL + c0);
    op[0] = __floats2half2_rn(dx * rstd * (1.0f + scv.x) + shv.x,
                              dy * rstd * (1.0f + scv.y) + shv.y);
    op[1] = __floats2half2_rn(dz * rstd * (1.0f + scv.z) + shv.z,
                              dw * rstd * (1.0f + scv.w) + shv.w);
}

// ---------------------------------------------------------------------------
// Kernel 3: FP16 mma.sync GEMM (m16n8k16, fp32 accum), cp.async 3-stage
// pipeline, ONE sync/tile. 8 warps, warp tile 64x32, ldmatrix fragments.
// A: half [M][K] row-major; Bt: half [N][K] (pre-transposed).
//   EPI 1: C = half(gelu(acc + bias[n]))        (feeds W2 GEMM)
//   EPI 2: C = res + gate * (acc + bias[n])     (fp32; exact residual)
//   EPI 3: qkv split: col<1024 -> q (+bias), else kv (+bias2); tf32 fp32 out
// ---------------------------------------------------------------------------
#define GSTAGES 3
#define HPAD 40   // halfs per row (80 B): ldmatrix rows 0..7 hit distinct banks
#define GEMM_SMEM_BYTES (GSTAGES * 2 * 128 * HPAD * (int)sizeof(__half))

template <int EPI>
__global__ void __launch_bounds__(256, 2) mma_gemm_kernel(
    const __half* __restrict__ A, const __half* __restrict__ Bt,
    const float* __restrict__ bias, const float* __restrict__ bias2,
    const float* __restrict__ res, const float* __restrict__ gate,
    void* __restrict__ Cv, float* __restrict__ C2,
    int M, int N, int K)
{
    extern __shared__ char smemRaw[];
    __half (*As)[128][HPAD] = reinterpret_cast<__half(*)[128][HPAD]>(smemRaw);
    __half (*Bs)[128][HPAD] = reinterpret_cast<__half(*)[128][HPAD]>(
        smemRaw + GSTAGES * 128 * HPAD * sizeof(__half));

    const int tid  = threadIdx.x;
    const int lane = tid & 31;
    const int warp = tid >> 5;
    const int wm   = warp & 1;
    const int wn   = warp >> 1;
    const int bm   = blockIdx.y * 128;
    const int bn   = blockIdx.x * 128;

    const int g  = lane >> 2;
    const int tg = lane & 3;

    float acc[4][4][4];
    #pragma unroll
    for (int i = 0; i < 4; i++)
        #pragma unroll
        for (int j = 0; j < 4; j++)
            #pragma unroll
            for (int r = 0; r < 4; r++) acc[i][j][r] = 0.f;

    const int kTiles = K >> 5;   // 32 halfs per k-tile

    // loader: 2 chunks A + 2 chunks B per thread per stage (16B each)
    auto load_tile = [&](int st, int k0) {
        #pragma unroll
        for (int i = 0; i < 2; i++) {
            int ch = tid + i * 256;          // 0..511
            int r = ch >> 2, sl = (ch & 3) * 8;
            cp_async16(&As[st][r][sl], A  + (size_t)(bm + r) * K + k0 + sl);
            cp_async16(&Bs[st][r][sl], Bt + (size_t)(bn + r) * K + k0 + sl);
        }
    };

    #pragma unroll
    for (int s = 0; s < GSTAGES - 1; s++) {
        load_tile(s, s * 32);
        cp_commit();
    }

    for (int it = 0; it < kTiles; it++) {
        cp_wait<GSTAGES - 2>();
        __syncthreads();

        int nxt = it + GSTAGES - 1;
        if (nxt < kTiles)
            load_tile(nxt % GSTAGES, nxt * 32);
        cp_commit();

        const int st = it % GSTAGES;
        #pragma unroll
        for (int ks = 0; ks < 2; ks++) {
            const int kb = ks * 16;
            uint32_t a[4][4], b[4][2];
            #pragma unroll
            for (int mf = 0; mf < 4; mf++) {
                int rowBase = wm * 64 + mf * 16;
                const __half* ap = &As[st][rowBase + (lane & 15)]
                                        [kb + ((lane >> 4) << 3)];
                ldsm_x4(a[mf], (uint32_t)__cvta_generic_to_shared(ap));
            }
            #pragma unroll
            for (int nf = 0; nf < 4; nf++) {
                int nBase = wn * 32 + nf * 8;
                const __half* bp = &Bs[st][nBase + (lane & 7)]
                                        [kb + (((lane >> 3) & 1) << 3)];
                ldsm_x2(b[nf], (uint32_t)__cvta_generic_to_shared(bp));
            }
            #pragma unroll
            for (int mf = 0; mf < 4; mf++)
                #pragma unroll
                for (int nf = 0; nf < 4; nf++)
                    mma_f16(acc[mf][nf][0], acc[mf][nf][1],
                            acc[mf][nf][2], acc[mf][nf][3],
                            a[mf][0], a[mf][1], a[mf][2], a[mf][3],
                            b[nf][0], b[nf][1]);
        }
    }

    #pragma unroll
    for (int mf = 0; mf < 4; mf++) {
        #pragma unroll
        for (int half_ = 0; half_ < 2; half_++) {
            int row = bm + wm * 64 + mf * 16 + g + half_ * 8;
            size_t gbase = (size_t)(row >> 10) * SIXD;
            #pragma unroll
            for (int nf = 0; nf < 4; nf++) {
                int col = bn + wn * 32 + nf * 8 + 2 * tg;
                float y0 = acc[mf][nf][half_ * 2 + 0];
                float y1 = acc[mf][nf][half_ * 2 + 1];
                if (EPI == 3) {
                    float* q = (float*)Cv;
                    if (col < DMODEL) {
                        size_t rb = (size_t)row * DMODEL;
                        q[rb + col]     = to_tf32(y0 + bias[col]);
                        q[rb + col + 1] = to_tf32(y1 + bias[col + 1]);
                    } else {
                        int c2 = col - DMODEL;
                        size_t rb = (size_t)row * (2 * DMODEL);
                        C2[rb + c2]     = to_tf32(y0 + bias2[c2]);
                        C2[rb + c2 + 1] = to_tf32(y1 + bias2[c2 + 1]);
                    }
                } else if (EPI == 1) {
                    __half* Ch = (__half*)Cv;
                    size_t rbase = (size_t)row * N;
                    *(__half2*)(Ch + rbase + col) =
                        __floats2half2_rn(gelu_tanh(y0 + bias[col]),
                                          gelu_tanh(y1 + bias[col + 1]));
                } else {
                    float* Cf = (float*)Cv;
                    size_t rbase = (size_t)row * N;
                    Cf[rbase + col]     = res[rbase + col]
                        + gate[gbase + col]     * (y0 + bias[col]);
                    Cf[rbase + col + 1] = res[rbase + col + 1]
                        + gate[gbase + col + 1] * (y1 + bias[col + 1]);
                }
            }
        }
    }
}

// ---------------------------------------------------------------------------
// Kernel 4: flash attention on tf32 tensor cores (R15 winner, unchanged math)
// 8 warps x m16 = 128 q rows per block, Bc=64, d=64.
// K/V for tile jt+1 prefetched into registers during tile jt's PV compute.
// Output converted to fp16 (att feeds the Wo GEMM as A).
// ---------------------------------------------------------------------------
#define AQ_PAD 68
#define AK_PAD 68
#define AV_PAD 72
#define AP_PAD 68
#define ATTN_SMEM_BYTES ((128 * AQ_PAD + 64 * AK_PAD + 64 * AV_PAD + 128 * AP_PAD) * (int)sizeof(float))

__global__ void __launch_bounds__(256, 2) attn_mma_kernel(
    const float* __restrict__ q, const float* __restrict__ kv,
    __half* __restrict__ out)
{
    extern __shared__ float sm[];
    float (*Qs)[AQ_PAD] = reinterpret_cast<float(*)[AQ_PAD]>(sm);
    float (*Ks)[AK_PAD] = reinterpret_cast<float(*)[AK_PAD]>(sm + 128 * AQ_PAD);
    float (*Vs)[AV_PAD] = reinterpret_cast<float(*)[AV_PAD]>(sm + 128 * AQ_PAD + 64 * AK_PAD);
    float (*Ps)[AP_PAD] = reinterpret_cast<float(*)[AP_PAD]>(sm + 128 * AQ_PAD + 64 * AK_PAD + 64 * AV_PAD);

    const int tid  = threadIdx.x;
    const int lane = tid & 31;
    const int warp = tid >> 5;
    const int g    = lane >> 2;
    const int tg   = lane & 3;
    const int b    = blockIdx.y >> 4;
    const int h    = blockIdx.y & 15;
    const int q0   = blockIdx.x * 128;
    const int rg   = warp * 16 + g;

    const int kvRow[4] = { tid >> 4, (tid + 256) >> 4, (tid + 512) >> 4, (tid + 768) >> 4 };
    const int kvD4 = (tid & 15) * 4;

    for (int t = tid; t < 128 * 16; t += 256) {
        int r = t >> 4, d4 = (t & 15) * 4;
        float4 v = *(const float4*)(q +
            ((((size_t)(b * NTOK + q0 + r)) * HEADS + h) << 6) + d4);
        Qs[r][d4 + 0] = v.x * 0.125f; Qs[r][d4 + 1] = v.y * 0.125f;
        Qs[r][d4 + 2] = v.z * 0.125f; Qs[r][d4 + 3] = v.w * 0.125f;
    }

    float o[8][4];
    #pragma unroll
    for (int nf = 0; nf < 8; nf++)
        #pragma unroll
        for (int r = 0; r < 4; r++) o[nf][r] = 0.f;
    float m0 = -INFINITY, m1 = -INFINITY, l0 = 0.f, l1 = 0.f;

    float4 kreg[4], vreg[4];
    #pragma unroll
    for (int i = 0; i < 4; i++) {
        size_t base = (size_t)(b * NTOK + kvRow[i]) * (2 * DMODEL) + h * HDIM + kvD4;
        kreg[i] = *(const float4*)(kv + base);
        vreg[i] = *(const float4*)(kv + base + DMODEL);
    }

    for (int jt = 0; jt < NTOK / 64; jt++) {
        __syncthreads();
        #pragma unroll
        for (int i = 0; i < 4; i++) {
            int r = kvRow[i];
            Ks[r][kvD4 + 0] = kreg[i].x; Ks[r][kvD4 + 1] = kreg[i].y;
            Ks[r][kvD4 + 2] = kreg[i].z; Ks[r][kvD4 + 3] = kreg[i].w;
            Vs[r][kvD4 + 0] = vreg[i].x; Vs[r][kvD4 + 1] = vreg[i].y;
            Vs[r][kvD4 + 2] = vreg[i].z; Vs[r][kvD4 + 3] = vreg[i].w;
        }
        __syncthreads();

        float s[8][4];
        #pragma unroll
        for (int nf = 0; nf < 8; nf++)
            #pragma unroll
            for (int r = 0; r < 4; r++) s[nf][r] = 0.f;
        #pragma unroll
        for (int kb = 0; kb < 64; kb += 8) {
            uint32_t a0 = __float_as_uint(Qs[rg    ][kb + tg    ]);
            uint32_t a1 = __float_as_uint(Qs[rg + 8][kb + tg    ]);
            uint32_t a2 = __float_as_uint(Qs[rg    ][kb + tg + 4]);
            uint32_t a3 = __float_as_uint(Qs[rg + 8][kb + tg + 4]);
            #pragma unroll
            for (int nf = 0; nf < 8; nf++) {
                uint32_t b0 = __float_as_uint(Ks[nf * 8 + g][kb + tg    ]);
                uint32_t b1 = __float_as_uint(Ks[nf * 8 + g][kb + tg + 4]);
                mma_tf32(s[nf][0], s[nf][1], s[nf][2], s[nf][3],
                         a0, a1, a2, a3, b0, b1);
            }
        }

        float mx0 = -INFINITY, mx1 = -INFINITY;
        #pragma unroll
        for (int nf = 0; nf < 8; nf++) {
            mx0 = fmaxf(mx0, fmaxf(s[nf][0], s[nf][1]));
            mx1 = fmaxf(mx1, fmaxf(s[nf][2], s[nf][3]));
        }
        mx0 = fmaxf(mx0, __shfl_xor_sync(0xffffffffu, mx0, 1));
        mx0 = fmaxf(mx0, __shfl_xor_sync(0xffffffffu, mx0, 2));
        mx1 = fmaxf(mx1, __shfl_xor_sync(0xffffffffu, mx1, 1));
        mx1 = fmaxf(mx1, __shfl_xor_sync(0xffffffffu, mx1, 2));
        float mN0 = fmaxf(m0, mx0), mN1 = fmaxf(m1, mx1);
        float c0 = __expf(m0 - mN0), c1 = __expf(m1 - mN1);
        float sum0 = 0.f, sum1 = 0.f;
        #pragma unroll
        for (int nf = 0; nf < 8; nf++) {
            s[nf][0] = __expf(s[nf][0] - mN0); sum0 += s[nf][0];
            s[nf][1] = __expf(s[nf][1] - mN0); sum0 += s[nf][1];
            s[nf][2] = __expf(s[nf][2] - mN1); sum1 += s[nf][2];
            s[nf][3] = __expf(s[nf][3] - mN1); sum1 += s[nf][3];
        }
        sum0 += __shfl_xor_sync(0xffffffffu, sum0, 1);
        sum0 += __shfl_xor_sync(0xffffffffu, sum0, 2);
        sum1 += __shfl_xor_sync(0xffffffffu, sum1, 1);
        sum1 += __shfl_xor_sync(0xffffffffu, sum1, 2);
        l0 = l0 * c0 + sum0; l1 = l1 * c1 + sum1;
        m0 = mN0; m1 = mN1;
        #pragma unroll
        for (int nf = 0; nf < 8; nf++) {
            o[nf][0] *= c0; o[nf][1] *= c0;
            o[nf][2] *= c1; o[nf][3] *= c1;
        }

        #pragma unroll
        for (int nf = 0; nf < 8; nf++) {
            int col = nf * 8 + 2 * tg;
            Ps[rg    ][col] = to_tf32(s[nf][0]); Ps[rg    ][col + 1] = to_tf32(s[nf][1]);
            Ps[rg + 8][col] = to_tf32(s[nf][2]); Ps[rg + 8][col + 1] = to_tf32(s[nf][3]);
        }
        __syncwarp();

        if (jt + 1 < NTOK / 64) {
            int j0n = (jt + 1) * 64;
            #pragma unroll
            for (int i = 0; i < 4; i++) {
                size_t base = (size_t)(b * NTOK + j0n + kvRow[i]) * (2 * DMODEL)
                            + h * HDIM + kvD4;
                kreg[i] = *(const float4*)(kv + base);
                vreg[i] = *(const float4*)(kv + base + DMODEL);
            }
        }

        #pragma unroll
        for (int kb = 0; kb < 64; kb += 8) {
            uint32_t a0 = __float_as_uint(Ps[rg    ][kb + tg    ]);
            uint32_t a1 = __float_as_uint(Ps[rg + 8][kb + tg    ]);
            uint32_t a2 = __float_as_uint(Ps[rg    ][kb + tg + 4]);
            uint32_t a3 = __float_as_uint(Ps[rg + 8][kb + tg + 4]);
            #pragma unroll
            for (int nf = 0; nf < 8; nf++) {
                uint32_t b0 = __float_as_uint(Vs[kb + tg    ][nf * 8 + g]);
                uint32_t b1 = __float_as_uint(Vs[kb + tg + 4][nf * 8 + g]);
                mma_tf32(o[nf][0], o[nf][1], o[nf][2], o[nf][3],
                         a0, a1, a2, a3, b0, b1);
            }
        }
    }

    float inv0 = 1.0f / l0, inv1 = 1.0f / l1;
    size_t row0 = ((((size_t)(b * NTOK + q0 + rg)) * HEADS + h) << 6);
    size_t row1 = ((((size_t)(b * NTOK + q0 + rg + 8)) * HEADS + h) << 6);
    #pragma unroll
    for (int nf = 0; nf < 8; nf++) {
        int col = nf * 8 + 2 * tg;
        *(__half2*)(out + row0 + col) =
            __floats2half2_rn(o[nf][0] * inv0, o[nf][1] * inv0);
        *(__half2*)(out + row1 + col) =
            __floats2half2_rn(o[nf][2] * inv1, o[nf][3] * inv1);
    }
}

// ---------------------------------------------------------------------------
// Launch
// ---------------------------------------------------------------------------
extern "C" void kernel_launch(void* const* d_in, const int* in_sizes, int n_in,
                              void* d_out, int out_size)
{
    const float* x    = (const float*)d_in[0];
    const float* c    = (const float*)d_in[1];
    const float* Wq   = (const float*)d_in[2];
    const float* bq   = (const float*)d_in[3];
    const float* Wkv  = (const float*)d_in[4];
    const float* bkv  = (const float*)d_in[5];
    const float* Wo   = (const float*)d_in[6];
    const float* bo   = (const float*)d_in[7];
    const float* W1   = (const float*)d_in[8];
    const float* b1   = (const float*)d_in[9];
    const float* W2   = (const float*)d_in[10];
    const float* b2   = (const float*)d_in[11];
    const float* Wada = (const float*)d_in[12];
    const float* bada = (const float*)d_in[13];
    float* out = (float*)d_out;

    float *mod, *q, *kv;
    __half *h, *att, *m1, *wqkv, *wo, *w1, *w2;
    cudaGetSymbolAddress((void**)&mod,  g_mod);
    cudaGetSymbolAddress((void**)&h,    g_h);
    cudaGetSymbolAddress((void**)&q,    g_q);
    cudaGetSymbolAddress((void**)&kv,   g_kv);
    cudaGetSymbolAddress((void**)&att,  g_att);
    cudaGetSymbolAddress((void**)&m1,   g_m1);
    cudaGetSymbolAddress((void**)&wqkv, g_wqkv);
    cudaGetSymbolAddress((void**)&wo,   g_wo);
    cudaGetSymbolAddress((void**)&w1,   g_w1);
    cudaGetSymbolAddress((void**)&w2,   g_w2);

    cudaFuncSetAttribute(attn_mma_kernel,
                         cudaFuncAttributeMaxDynamicSharedMemorySize, ATTN_SMEM_BYTES);
    cudaFuncSetAttribute(mma_gemm_kernel<1>,
                         cudaFuncAttributeMaxDynamicSharedMemorySize, GEMM_SMEM_BYTES);
    cudaFuncSetAttribute(mma_gemm_kernel<2>,
                         cudaFuncAttributeMaxDynamicSharedMemorySize, GEMM_SMEM_BYTES);
    cudaFuncSetAttribute(mma_gemm_kernel<3>,
                         cudaFuncAttributeMaxDynamicSharedMemorySize, GEMM_SMEM_BYTES);

    // 0) transpose + convert all weights -> half [N][K]
    transpose_half_kernel<<<dim3(4096, 5), dim3(32, 8)>>>(
        Wq, Wkv, Wo, W1, W2, wqkv, wo, w1, w2);

    // 1) adaLN modulation
    ada_mod_kernel<<<dim3(SIXD / 256, BATCH), 256>>>(c, Wada, bada, mod);

    // 2) h = fp16(modulate(LN(x), sh_msa, sc_msa))
    ln_mod_kernel<<<ROWS, 256>>>(x, mod, 0 * DMODEL, 1 * DMODEL, h);

    // 3) fused QKV GEMM (fp16): [q | kv] = h @ [Wq | Wkv] + [bq | bkv]
    mma_gemm_kernel<3><<<dim3(3 * DMODEL / 128, ROWS / 128), 256, GEMM_SMEM_BYTES>>>(
        h, wqkv, bq, bkv, nullptr, nullptr, q, kv, ROWS, 3 * DMODEL, DMODEL);

    // 4) attention (tf32 flash; fp16 att out)
    attn_mma_kernel<<<dim3(NTOK / 128, BATCH * HEADS), 256, ATTN_SMEM_BYTES>>>(q, kv, att);

    // 5) x1 = x + g_msa * (att @ Wo + bo)   -> d_out (fp32)
    mma_gemm_kernel<2><<<dim3(DMODEL / 128, ROWS / 128), 256, GEMM_SMEM_BYTES>>>(
        att, wo, bo, nullptr, x, mod + 2 * DMODEL, out, nullptr, ROWS, DMODEL, DMODEL);

    // 6) h2 = fp16(modulate(LN(x1), sh_mlp, sc_mlp))
    ln_mod_kernel<<<ROWS, 256>>>(out, mod, 3 * DMODEL, 4 * DMODEL, h);

    // 7) m1 = fp16(gelu(h2 @ W1 + b1))
    mma_gemm_kernel<1><<<dim3(MLPD / 128, ROWS / 128), 256, GEMM_SMEM_BYTES>>>(
        h, w1, b1, nullptr, nullptr, nullptr, m1, nullptr, ROWS, MLPD, DMODEL);

    // 8) x2 = x1 + g_mlp * (m1 @ W2 + b2)   -> d_out (fp32)
    mma_gemm_kernel<2><<<dim3(DMODEL / 128, ROWS / 128), 256, GEMM_SMEM_BYTES>>>(
        m1, w2, b2, nullptr, out, mod + 5 * DMODEL, out, nullptr, ROWS, DMODEL, MLPD);
}

// round 17
// speedup vs baseline: 1.7567x; 1.1222x over previous
#include <cuda_runtime.h>
#include <cuda_fp16.h>
#include <math.h>
#include <stdint.h>

// ---------------------------------------------------------------------------
// Problem constants
// ---------------------------------------------------------------------------
#define BATCH  4
#define NTOK   1024
#define DMODEL 1024
#define HEADS  16
#define HDIM   64
#define ROWS   (BATCH * NTOK)     // 4096
#define MLPD   4096
#define SIXD   (6 * DMODEL)       // 6144
#define EPS    1e-6f

// ---------------------------------------------------------------------------
// Scratch (device globals: no allocations allowed)
// ---------------------------------------------------------------------------
__device__ float  g_mod[BATCH * SIXD];
__device__ __half g_h  [ROWS * DMODEL];      // fp16 (GEMM A operand)
__device__ __half g_q  [ROWS * DMODEL];      // fp16 (attention input)
__device__ __half g_kv [ROWS * 2 * DMODEL];  // fp16 (attention input)
__device__ __half g_att[ROWS * DMODEL];      // fp16 (Wo A operand)
__device__ __half g_m1 [ROWS * MLPD];        // fp16 (W2 A operand)
// fp16, TRANSPOSED weights [N][K]; Wq|Wkv stacked into [3072][1024]
__device__ __half g_wqkv[3 * DMODEL * DMODEL];
__device__ __half g_wo  [DMODEL * DMODEL];
__device__ __half g_w1  [MLPD * DMODEL];
__device__ __half g_w2  [DMODEL * MLPD];

// ---------------------------------------------------------------------------
// Helpers
// ---------------------------------------------------------------------------
__device__ __forceinline__ float gelu_tanh(float y) {
    float y3 = y * y * y;
    return 0.5f * y * (1.0f + tanhf(0.7978845608028654f * (y + 0.044715f * y3)));
}

__device__ __forceinline__ void cp_async16(void* smem_dst, const void* gmem_src) {
    uint32_t s = (uint32_t)__cvta_generic_to_shared(smem_dst);
    asm volatile("cp.async.cg.shared.global [%0], [%1], 16;\n"
                 :: "r"(s), "l"(gmem_src));
}
__device__ __forceinline__ void cp_commit() {
    asm volatile("cp.async.commit_group;\n");
}
template <int N>
__device__ __forceinline__ void cp_wait() {
    asm volatile("cp.async.wait_group %0;\n" :: "n"(N));
}

// fp16 mma, fp32 accumulate
__device__ __forceinline__ void mma_f16(
    float& d0, float& d1, float& d2, float& d3,
    uint32_t a0, uint32_t a1, uint32_t a2, uint32_t a3,
    uint32_t b0, uint32_t b1)
{
    asm volatile(
        "mma.sync.aligned.m16n8k16.row.col.f32.f16.f16.f32 "
        "{%0,%1,%2,%3}, {%4,%5,%6,%7}, {%8,%9}, {%0,%1,%2,%3};"
        : "+f"(d0), "+f"(d1), "+f"(d2), "+f"(d3)
        : "r"(a0), "r"(a1), "r"(a2), "r"(a3), "r"(b0), "r"(b1));
}

__device__ __forceinline__ void ldsm_x4(uint32_t* r, uint32_t addr) {
    asm volatile("ldmatrix.sync.aligned.m8n8.x4.shared.b16 {%0,%1,%2,%3}, [%4];"
                 : "=r"(r[0]), "=r"(r[1]), "=r"(r[2]), "=r"(r[3]) : "r"(addr));
}
__device__ __forceinline__ void ldsm_x2(uint32_t* r, uint32_t addr) {
    asm volatile("ldmatrix.sync.aligned.m8n8.x2.shared.b16 {%0,%1}, [%2];"
                 : "=r"(r[0]), "=r"(r[1]) : "r"(addr));
}
__device__ __forceinline__ void ldsm_x2_trans(uint32_t* r, uint32_t addr) {
    asm volatile("ldmatrix.sync.aligned.m8n8.x2.trans.shared.b16 {%0,%1}, [%2];"
                 : "=r"(r[0]), "=r"(r[1]) : "r"(addr));
}

__device__ __forceinline__ uint32_t f2h2(float a, float b) {
    __half2 h = __floats2half2_rn(a, b);
    return *(uint32_t*)&h;
}

// ---------------------------------------------------------------------------
// Kernel 0: transpose + fp16-convert weights: src fp32 [K][N] -> dst half [N][K]
// ---------------------------------------------------------------------------
__global__ void __launch_bounds__(256) transpose_half_kernel(
    const float* __restrict__ Wq, const float* __restrict__ Wkv,
    const float* __restrict__ Wo, const float* __restrict__ W1,
    const float* __restrict__ W2,
    __half* __restrict__ wqkvT, __half* __restrict__ woT,
    __half* __restrict__ w1T, __half* __restrict__ w2T)
{
    __shared__ float s[32][33];
    const int t = blockIdx.y;
    const int i = blockIdx.x;
    const float* src = nullptr;
    __half* dst = nullptr;
    int K = 0, N = 0, rowOff = 0;
    switch (t) {
        case 0: src = Wq;  dst = wqkvT; K = 1024; N = 1024; rowOff = 0;    break;
        case 1: src = Wkv; dst = wqkvT; K = 1024; N = 2048; rowOff = 1024; break;
        case 2: src = Wo;  dst = woT;   K = 1024; N = 1024; rowOff = 0;    break;
        case 3: src = W1;  dst = w1T;   K = 1024; N = 4096; rowOff = 0;    break;
        case 4: src = W2;  dst = w2T;   K = 4096; N = 1024; rowOff = 0;    break;
    }
    const int ntx = N >> 5;
    if (i >= (K >> 5) * ntx) return;
    const int kb = i / ntx, nb = i % ntx;
    const int tx = threadIdx.x, ty = threadIdx.y;

    #pragma unroll
    for (int j = 0; j < 4; j++) {
        int r = ty + j * 8;
        s[r][tx] = src[(size_t)(kb * 32 + r) * N + nb * 32 + tx];
    }
    __syncthreads();
    #pragma unroll
    for (int j = 0; j < 4; j++) {
        int r = ty + j * 8;
        dst[(size_t)(rowOff + nb * 32 + r) * K + kb * 32 + tx] =
            __float2half_rn(s[tx][r]);
    }
}

// ---------------------------------------------------------------------------
// Kernel 1: mod = silu(c) @ Wada + bada        [4, 6144]
// ---------------------------------------------------------------------------
__global__ void __launch_bounds__(256) ada_mod_kernel(
    const float* __restrict__ c, const float* __restrict__ Wada,
    const float* __restrict__ bada, float* __restrict__ mod)
{
    __shared__ float sc[DMODEL];
    int b = blockIdx.y;
    int n = blockIdx.x * 256 + threadIdx.x;
    for (int i = threadIdx.x; i < DMODEL; i += 256) {
        float v = c[b * DMODEL + i];
        sc[i] = v / (1.0f + __expf(-v));
    }
    __syncthreads();
    float acc = 0.0f;
    const float* wp = Wada + n;
    for (int k = 0; k < DMODEL; k++)
        acc = fmaf(sc[k], wp[(size_t)k * SIXD], acc);
    mod[b * SIXD + n] = acc + bada[n];
}

// ---------------------------------------------------------------------------
// Kernel 2: out = fp16(LN(x) * (1 + scale) + shift)
// ---------------------------------------------------------------------------
__global__ void __launch_bounds__(256) ln_mod_kernel(
    const float* __restrict__ x, const float* __restrict__ mod,
    int shiftOff, int scaleOff, __half* __restrict__ out)
{
    __shared__ float red[8];
    int row = blockIdx.x;
    int b = row >> 10;
    const float4* xr = (const float4*)(x + (size_t)row * DMODEL);
    float4 v = xr[threadIdx.x];

    float s = v.x + v.y + v.z + v.w;
    #pragma unroll
    for (int o = 16; o; o >>= 1) s += __shfl_xor_sync(0xffffffffu, s, o);
    if ((threadIdx.x & 31) == 0) red[threadIdx.x >> 5] = s;
    __syncthreads();
    float tot = 0.f;
    #pragma unroll
    for (int w = 0; w < 8; w++) tot += red[w];
    float mean = tot * (1.0f / DMODEL);
    __syncthreads();

    float dx = v.x - mean, dy = v.y - mean, dz = v.z - mean, dw = v.w - mean;
    float q = dx * dx + dy * dy + dz * dz + dw * dw;
    #pragma unroll
    for (int o = 16; o; o >>= 1) q += __shfl_xor_sync(0xffffffffu, q, o);
    if ((threadIdx.x & 31) == 0) red[threadIdx.x >> 5] = q;
    __syncthreads();
    float vtot = 0.f;
    #pragma unroll
    for (int w = 0; w < 8; w++) vtot += red[w];
    float rstd = rsqrtf(vtot * (1.0f / DMODEL) + EPS);

    int c0 = threadIdx.x * 4;
    const float* base = mod + (size_t)b * SIXD;
    float4 shv = *(const float4*)(base + shiftOff + c0);
    float4 scv = *(const float4*)(base + scaleOff + c0);
    __half2* op = (__half2*)(out + (size_t)row * DMODEL + c0);
    op[0] = __floats2half2_rn(dx * rstd * (1.0f + scv.x) + shv.x,
                              dy * rstd * (1.0f + scv.y) + shv.y);
    op[1] = __floats2half2_rn(dz * rstd * (1.0f + scv.z) + shv.z,
                              dw * rstd * (1.0f + scv.w) + shv.w);
}

// ---------------------------------------------------------------------------
// Kernel 3: FP16 mma.sync GEMM (m16n8k16, fp32 accum), cp.async 4-stage
// pipeline, ONE sync/tile. 8 warps, warp tile 64x32, ldmatrix fragments.
//   EPI 1: C = half(gelu(acc + bias[n]))        (feeds W2 GEMM)
//   EPI 2: C = res + gate * (acc + bias[n])     (fp32; exact residual)
//   EPI 3: qkv split: col<1024 -> q (+bias), else kv (+bias2); half out
// ---------------------------------------------------------------------------
#define GSTAGES 4
#define HPAD 40
#define GEMM_SMEM_BYTES (GSTAGES * 2 * 128 * HPAD * (int)sizeof(__half))

template <int EPI>
__global__ void __launch_bounds__(256, 2) mma_gemm_kernel(
    const __half* __restrict__ A, const __half* __restrict__ Bt,
    const float* __restrict__ bias, const float* __restrict__ bias2,
    const float* __restrict__ res, const float* __restrict__ gate,
    void* __restrict__ Cv, __half* __restrict__ C2,
    int M, int N, int K)
{
    extern __shared__ char smemRaw[];
    __half (*As)[128][HPAD] = reinterpret_cast<__half(*)[128][HPAD]>(smemRaw);
    __half (*Bs)[128][HPAD] = reinterpret_cast<__half(*)[128][HPAD]>(
        smemRaw + GSTAGES * 128 * HPAD * sizeof(__half));

    const int tid  = threadIdx.x;
    const int lane = tid & 31;
    const int warp = tid >> 5;
    const int wm   = warp & 1;
    const int wn   = warp >> 1;
    const int bm   = blockIdx.y * 128;
    const int bn   = blockIdx.x * 128;

    const int g  = lane >> 2;
    const int tg = lane & 3;

    float acc[4][4][4];
    #pragma unroll
    for (int i = 0; i < 4; i++)
        #pragma unroll
        for (int j = 0; j < 4; j++)
            #pragma unroll
            for (int r = 0; r < 4; r++) acc[i][j][r] = 0.f;

    const int kTiles = K >> 5;

    auto load_tile = [&](int st, int k0) {
        #pragma unroll
        for (int i = 0; i < 2; i++) {
            int ch = tid + i * 256;
            int r = ch >> 2, sl = (ch & 3) * 8;
            cp_async16(&As[st][r][sl], A  + (size_t)(bm + r) * K + k0 + sl);
            cp_async16(&Bs[st][r][sl], Bt + (size_t)(bn + r) * K + k0 + sl);
        }
    };

    #pragma unroll
    for (int s = 0; s < GSTAGES - 1; s++) {
        load_tile(s, s * 32);
        cp_commit();
    }

    for (int it = 0; it < kTiles; it++) {
        cp_wait<GSTAGES - 2>();
        __syncthreads();

        int nxt = it + GSTAGES - 1;
        if (nxt < kTiles)
            load_tile(nxt % GSTAGES, nxt * 32);
        cp_commit();

        const int st = it % GSTAGES;
        #pragma unroll
        for (int ks = 0; ks < 2; ks++) {
            const int kb = ks * 16;
            uint32_t a[4][4], b[4][2];
            #pragma unroll
            for (int mf = 0; mf < 4; mf++) {
                int rowBase = wm * 64 + mf * 16;
                const __half* ap = &As[st][rowBase + (lane & 15)]
                                        [kb + ((lane >> 4) << 3)];
                ldsm_x4(a[mf], (uint32_t)__cvta_generic_to_shared(ap));
            }
            #pragma unroll
            for (int nf = 0; nf < 4; nf++) {
                int nBase = wn * 32 + nf * 8;
                const __half* bp = &Bs[st][nBase + (lane & 7)]
                                        [kb + (((lane >> 3) & 1) << 3)];
                ldsm_x2(b[nf], (uint32_t)__cvta_generic_to_shared(bp));
            }
            #pragma unroll
            for (int mf = 0; mf < 4; mf++)
                #pragma unroll
                for (int nf = 0; nf < 4; nf++)
                    mma_f16(acc[mf][nf][0], acc[mf][nf][1],
                            acc[mf][nf][2], acc[mf][nf][3],
                            a[mf][0], a[mf][1], a[mf][2], a[mf][3],
                            b[nf][0], b[nf][1]);
        }
    }

    #pragma unroll
    for (int mf = 0; mf < 4; mf++) {
        #pragma unroll
        for (int half_ = 0; half_ < 2; half_++) {
            int row = bm + wm * 64 + mf * 16 + g + half_ * 8;
            size_t gbase = (size_t)(row >> 10) * SIXD;
            #pragma unroll
            for (int nf = 0; nf < 4; nf++) {
                int col = bn + wn * 32 + nf * 8 + 2 * tg;
                float y0 = acc[mf][nf][half_ * 2 + 0];
                float y1 = acc[mf][nf][half_ * 2 + 1];
                if (EPI == 3) {
                    __half* q = (__half*)Cv;
                    if (col < DMODEL) {
                        size_t rb = (size_t)row * DMODEL;
                        *(__half2*)(q + rb + col) =
                            __floats2half2_rn(y0 + bias[col], y1 + bias[col + 1]);
                    } else {
                        int c2 = col - DMODEL;
                        size_t rb = (size_t)row * (2 * DMODEL);
                        *(__half2*)(C2 + rb + c2) =
                            __floats2half2_rn(y0 + bias2[c2], y1 + bias2[c2 + 1]);
                    }
                } else if (EPI == 1) {
                    __half* Ch = (__half*)Cv;
                    size_t rbase = (size_t)row * N;
                    *(__half2*)(Ch + rbase + col) =
                        __floats2half2_rn(gelu_tanh(y0 + bias[col]),
                                          gelu_tanh(y1 + bias[col + 1]));
                } else {
                    float* Cf = (float*)Cv;
                    size_t rbase = (size_t)row * N;
                    Cf[rbase + col]     = res[rbase + col]
                        + gate[gbase + col]     * (y0 + bias[col]);
                    Cf[rbase + col + 1] = res[rbase + col + 1]
                        + gate[gbase + col + 1] * (y1 + bias[col + 1]);
                }
            }
        }
    }
}

// ---------------------------------------------------------------------------
// Kernel 4: flash attention on fp16 tensor cores (m16n8k16, fp32 accum)
// 8 warps x m16 = 128 q rows per block, Bc=64, d=64.
// Q fragments hoisted (loop-invariant). P converted S-frag -> A-frag in
// registers (no smem round trip). V consumed via ldmatrix.trans.
// K/V for jt+1 register-prefetched during jt's PV compute.
// ---------------------------------------------------------------------------
#define AQ_HPAD 72
#define ATTN_SMEM_BYTES ((128 + 64 + 64) * AQ_HPAD * (int)sizeof(__half))

__global__ void __launch_bounds__(256, 2) attn_mma_kernel(
    const __half* __restrict__ q, const __half* __restrict__ kv,
    __half* __restrict__ out)
{
    extern __shared__ __half smh[];
    __half (*Qs)[AQ_HPAD] = reinterpret_cast<__half(*)[AQ_HPAD]>(smh);
    __half (*Ks)[AQ_HPAD] = reinterpret_cast<__half(*)[AQ_HPAD]>(smh + 128 * AQ_HPAD);
    __half (*Vs)[AQ_HPAD] = reinterpret_cast<__half(*)[AQ_HPAD]>(smh + 192 * AQ_HPAD);

    const int tid  = threadIdx.x;
    const int lane = tid & 31;
    const int warp = tid >> 5;
    const int g    = lane >> 2;
    const int tg   = lane & 3;
    const int b    = blockIdx.y >> 4;
    const int h    = blockIdx.y & 15;
    const int q0   = blockIdx.x * 128;

    // K/V staging slots: 2 rounds x (row, col8)
    const int kvRow[2] = { tid >> 3, (tid + 256) >> 3 };
    const int kvC8 = (tid & 7) * 8;

    // load Q tile (128 x 64 halfs)
    for (int t = tid; t < 128 * 8; t += 256) {
        int r = t >> 3, c8 = (t & 7) * 8;
        *(uint4*)&Qs[r][c8] = *(const uint4*)(q +
            ((((size_t)(b * NTOK + q0 + r)) * HEADS + h) << 6) + c8);
    }
    __syncthreads();

    // hoist Q fragments (invariant across j-tiles)
    uint32_t qf[4][4];
    {
        int rowBase = warp * 16;
        #pragma unroll
        for (int kb4 = 0; kb4 < 4; kb4++) {
            const __half* ap = &Qs[rowBase + (lane & 15)]
                                  [kb4 * 16 + ((lane >> 4) << 3)];
            ldsm_x4(qf[kb4], (uint32_t)__cvta_generic_to_shared(ap));
        }
    }

    float o[8][4];
    #pragma unroll
    for (int nf = 0; nf < 8; nf++)
        #pragma unroll
        for (int r = 0; r < 4; r++) o[nf][r] = 0.f;
    float m0 = -INFINITY, m1 = -INFINITY, l0 = 0.f, l1 = 0.f;

    // prologue prefetch (jt = 0)
    uint4 kreg[2], vreg[2];
    #pragma unroll
    for (int i = 0; i < 2; i++) {
        size_t base = (size_t)(b * NTOK + kvRow[i]) * (2 * DMODEL) + h * HDIM + kvC8;
        kreg[i] = *(const uint4*)(kv + base);
        vreg[i] = *(const uint4*)(kv + base + DMODEL);
    }

    for (int jt = 0; jt < NTOK / 64; jt++) {
        __syncthreads();   // WAR: previous iter's reads of Ks/Vs done
        #pragma unroll
        for (int i = 0; i < 2; i++) {
            *(uint4*)&Ks[kvRow[i]][kvC8] = kreg[i];
            *(uint4*)&Vs[kvRow[i]][kvC8] = vreg[i];
        }
        __syncthreads();

        // S = Q @ K^T (scale applied post-mma; exact: 0.125 = 2^-3)
        float s[8][4];
        #pragma unroll
        for (int nf = 0; nf < 8; nf++)
            #pragma unroll
            for (int r = 0; r < 4; r++) s[nf][r] = 0.f;
        #pragma unroll
        for (int kb4 = 0; kb4 < 4; kb4++) {
            const int kb = kb4 * 16;
            #pragma unroll
            for (int nf = 0; nf < 8; nf++) {
                uint32_t bfr[2];
                const __half* bp = &Ks[nf * 8 + (lane & 7)]
                                      [kb + (((lane >> 3) & 1) << 3)];
                ldsm_x2(bfr, (uint32_t)__cvta_generic_to_shared(bp));
                mma_f16(s[nf][0], s[nf][1], s[nf][2], s[nf][3],
                        qf[kb4][0], qf[kb4][1], qf[kb4][2], qf[kb4][3],
                        bfr[0], bfr[1]);
            }
        }
        #pragma unroll
        for (int nf = 0; nf < 8; nf++)
            #pragma unroll
            for (int r = 0; r < 4; r++) s[nf][r] *= 0.125f;

        // online softmax (rows warp*16+g and +8)
        float mx0 = -INFINITY, mx1 = -INFINITY;
        #pragma unroll
        for (int nf = 0; nf < 8; nf++) {
            mx0 = fmaxf(mx0, fmaxf(s[nf][0], s[nf][1]));
            mx1 = fmaxf(mx1, fmaxf(s[nf][2], s[nf][3]));
        }
        mx0 = fmaxf(mx0, __shfl_xor_sync(0xffffffffu, mx0, 1));
        mx0 = fmaxf(mx0, __shfl_xor_sync(0xffffffffu, mx0, 2));
        mx1 = fmaxf(mx1, __shfl_xor_sync(0xffffffffu, mx1, 1));
        mx1 = fmaxf(mx1, __shfl_xor_sync(0xffffffffu, mx1, 2));
        float mN0 = fmaxf(m0, mx0), mN1 = fmaxf(m1, mx1);
        float c0 = __expf(m0 - mN0), c1 = __expf(m1 - mN1);
        float sum0 = 0.f, sum1 = 0.f;
        #pragma unroll
        for (int nf = 0; nf < 8; nf++) {
            s[nf][0] = __expf(s[nf][0] - mN0); sum0 += s[nf][0];
            s[nf][1] = __expf(s[nf][1] - mN0); sum0 += s[nf][1];
            s[nf][2] = __expf(s[nf][2] - mN1); sum1 += s[nf][2];
            s[nf][3] = __expf(s[nf][3] - mN1); sum1 += s[nf][3];
        }
        sum0 += __shfl_xor_sync(0xffffffffu, sum0, 1);
        sum0 += __shfl_xor_sync(0xffffffffu, sum0, 2);
        sum1 += __shfl_xor_sync(0xffffffffu, sum1, 1);
        sum1 += __shfl_xor_sync(0xffffffffu, sum1, 2);
        l0 = l0 * c0 + sum0; l1 = l1 * c1 + sum1;
        m0 = mN0; m1 = mN1;
        #pragma unroll
        for (int nf = 0; nf < 8; nf++) {
            o[nf][0] *= c0; o[nf][1] *= c0;
            o[nf][2] *= c1; o[nf][3] *= c1;
        }

        // convert P: S-fragment -> PV A-fragment, pure registers (s dies here)
        uint32_t pf[4][4];
        #pragma unroll
        for (int kb4 = 0; kb4 < 4; kb4++) {
            int nf0 = kb4 * 2, nf1 = kb4 * 2 + 1;
            pf[kb4][0] = f2h2(s[nf0][0], s[nf0][1]);
            pf[kb4][1] = f2h2(s[nf0][2], s[nf0][3]);
            pf[kb4][2] = f2h2(s[nf1][0], s[nf1][1]);
            pf[kb4][3] = f2h2(s[nf1][2], s[nf1][3]);
        }

        // prefetch next tile's K/V (hidden under PV mma)
        if (jt + 1 < NTOK / 64) {
            int j0n = (jt + 1) * 64;
            #pragma unroll
            for (int i = 0; i < 2; i++) {
                size_t base = (size_t)(b * NTOK + j0n + kvRow[i]) * (2 * DMODEL)
                            + h * HDIM + kvC8;
                kreg[i] = *(const uint4*)(kv + base);
                vreg[i] = *(const uint4*)(kv + base + DMODEL);
            }
        }

        // O += P @ V  (V via ldmatrix.trans from [j][d] layout)
        #pragma unroll
        for (int kb4 = 0; kb4 < 4; kb4++) {
            const int kb = kb4 * 16;
            #pragma unroll
            for (int nf = 0; nf < 8; nf++) {
                uint32_t bfr[2];
                const __half* bp = &Vs[kb + (lane & 15)][nf * 8];
                ldsm_x2_trans(bfr, (uint32_t)__cvta_generic_to_shared(bp));
                mma_f16(o[nf][0], o[nf][1], o[nf][2], o[nf][3],
                        pf[kb4][0], pf[kb4][1], pf[kb4][2], pf[kb4][3],
                        bfr[0], bfr[1]);
            }
        }
    }

    float inv0 = 1.0f / l0, inv1 = 1.0f / l1;
    const int rg = warp * 16 + g;
    size_t row0 = ((((size_t)(b * NTOK + q0 + rg)) * HEADS + h) << 6);
    size_t row1 = ((((size_t)(b * NTOK + q0 + rg + 8)) * HEADS + h) << 6);
    #pragma unroll
    for (int nf = 0; nf < 8; nf++) {
        int col = nf * 8 + 2 * tg;
        *(__half2*)(out + row0 + col) =
            __floats2half2_rn(o[nf][0] * inv0, o[nf][1] * inv0);
        *(__half2*)(out + row1 + col) =
            __floats2half2_rn(o[nf][2] * inv1, o[nf][3] * inv1);
    }
}

// ---------------------------------------------------------------------------
// Launch
// ---------------------------------------------------------------------------
extern "C" void kernel_launch(void* const* d_in, const int* in_sizes, int n_in,
                              void* d_out, int out_size)
{
    const float* x    = (const float*)d_in[0];
    const float* c    = (const float*)d_in[1];
    const float* Wq   = (const float*)d_in[2];
    const float* bq   = (const float*)d_in[3];
    const float* Wkv  = (const float*)d_in[4];
    const float* bkv  = (const float*)d_in[5];
    const float* Wo   = (const float*)d_in[6];
    const float* bo   = (const float*)d_in[7];
    const float* W1   = (const float*)d_in[8];
    const float* b1   = (const float*)d_in[9];
    const float* W2   = (const float*)d_in[10];
    const float* b2   = (const float*)d_in[11];
    const float* Wada = (const float*)d_in[12];
    const float* bada = (const float*)d_in[13];
    float* out = (float*)d_out;

    float *mod;
    __half *h, *q, *kv, *att, *m1, *wqkv, *wo, *w1, *w2;
    cudaGetSymbolAddress((void**)&mod,  g_mod);
    cudaGetSymbolAddress((void**)&h,    g_h);
    cudaGetSymbolAddress((void**)&q,    g_q);
    cudaGetSymbolAddress((void**)&kv,   g_kv);
    cudaGetSymbolAddress((void**)&att,  g_att);
    cudaGetSymbolAddress((void**)&m1,   g_m1);
    cudaGetSymbolAddress((void**)&wqkv, g_wqkv);
    cudaGetSymbolAddress((void**)&wo,   g_wo);
    cudaGetSymbolAddress((void**)&w1,   g_w1);
    cudaGetSymbolAddress((void**)&w2,   g_w2);

    cudaFuncSetAttribute(attn_mma_kernel,
                         cudaFuncAttributeMaxDynamicSharedMemorySize, ATTN_SMEM_BYTES);
    cudaFuncSetAttribute(mma_gemm_kernel<1>,
                         cudaFuncAttributeMaxDynamicSharedMemorySize, GEMM_SMEM_BYTES);
    cudaFuncSetAttribute(mma_gemm_kernel<2>,
                         cudaFuncAttributeMaxDynamicSharedMemorySize, GEMM_SMEM_BYTES);
    cudaFuncSetAttribute(mma_gemm_kernel<3>,
                         cudaFuncAttributeMaxDynamicSharedMemorySize, GEMM_SMEM_BYTES);

    // 0) transpose + convert all weights -> half [N][K]
    transpose_half_kernel<<<dim3(4096, 5), dim3(32, 8)>>>(
        Wq, Wkv, Wo, W1, W2, wqkv, wo, w1, w2);

    // 1) adaLN modulation
    ada_mod_kernel<<<dim3(SIXD / 256, BATCH), 256>>>(c, Wada, bada, mod);

    // 2) h = fp16(modulate(LN(x), sh_msa, sc_msa))
    ln_mod_kernel<<<ROWS, 256>>>(x, mod, 0 * DMODEL, 1 * DMODEL, h);

    // 3) fused QKV GEMM (fp16): [q | kv] = h @ [Wq | Wkv] + [bq | bkv]
    mma_gemm_kernel<3><<<dim3(3 * DMODEL / 128, ROWS / 128), 256, GEMM_SMEM_BYTES>>>(
        h, wqkv, bq, bkv, nullptr, nullptr, q, kv, ROWS, 3 * DMODEL, DMODEL);

    // 4) attention (fp16 flash)
    attn_mma_kernel<<<dim3(NTOK / 128, BATCH * HEADS), 256, ATTN_SMEM_BYTES>>>(q, kv, att);

    // 5) x1 = x + g_msa * (att @ Wo + bo)   -> d_out (fp32)
    mma_gemm_kernel<2><<<dim3(DMODEL / 128, ROWS / 128), 256, GEMM_SMEM_BYTES>>>(
        att, wo, bo, nullptr, x, mod + 2 * DMODEL, out, nullptr, ROWS, DMODEL, DMODEL);

    // 6) h2 = fp16(modulate(LN(x1), sh_mlp, sc_mlp))
    ln_mod_kernel<<<ROWS, 256>>>(out, mod, 3 * DMODEL, 4 * DMODEL, h);

    // 7) m1 = fp16(gelu(h2 @ W1 + b1))
    mma_gemm_kernel<1><<<dim3(MLPD / 128, ROWS / 128), 256, GEMM_SMEM_BYTES>>>(
        h, w1, b1, nullptr, nullptr, nullptr, m1, nullptr, ROWS, MLPD, DMODEL);

    // 8) x2 = x1 + g_mlp * (m1 @ W2 + b2)   -> d_out (fp32)
    mma_gemm_kernel<2><<<dim3(DMODEL / 128, ROWS / 128), 256, GEMM_SMEM_BYTES>>>(
        m1, w2, b2, nullptr, out, mod + 5 * DMODEL, out, nullptr, ROWS, DMODEL, MLPD);
}